// round 6
// baseline (speedup 1.0000x reference)
#include <cuda_runtime.h>
#include <cuda_bf16.h>
#include <cstdint>

#define D 128
#define NA 100000
#define NB 150000
#define NG 2000
#define NTOT (NA + NB + NG)      // 252000
#define DEG_TOT 756000           // sum over rels of n_dst (= sum of n_src)
#define NE_TOT 1352000           // total edges over 9 relations
#define NTILES 5910              // sum over rels of ceil(ndst/128)
#define BN_EPS 1e-5f
#define SCAN_NB ((DEG_TOT + 1023) / 1024)   // 739

#define DOFF_INIT {0,150000,250000,252000,352000,354000,504000,604000,754000,756000}
#define SOFF_INIT {0,100000,250000,350000,352000,502000,504000,604000,754000,756000}
#define EOFF_INIT {0,300000,600000,700000,800000,950000,1100000,1200000,1350000,1352000}
#define TBASE_INIT {0,1172,1954,1970,2752,2768,3940,4722,5894,5910}
#define ST_INIT {0,1,0,2,1,2,0,1,2}

// ---------------- device scratch ----------------
__device__ int g_odeg[DEG_TOT];
__device__ int g_ideg[DEG_TOT];
__device__ int g_offs[DEG_TOT];
__device__ int g_cursor[DEG_TOT];
__device__ int g_bsum[SCAN_NB];
__device__ int g_eidx[NE_TOT];                    // CSR: rel-local src index
__device__ float g_ew[NE_TOT];                    // CSR: ns[src]
__device__ float g_ns[DEG_TOT];
__device__ float g_nd[DEG_TOT];
__device__ float g_gout[(size_t)DEG_TOT * D];     // gemm output (pre-BN), rel dst-major
__device__ float g_feat[(size_t)NTOT * D];        // layer-0 output
__device__ float g_stats[9 * 2 * D];
__device__ float g_scale[9 * D];
__device__ float g_shift[9 * D];
__device__ __align__(128) __nv_bfloat16 g_wh[18 * D * D];  // W hi, swizzled B-tile layout
__device__ __align__(128) __nv_bfloat16 g_wl[18 * D * D];  // W lo

__device__ const int d_ndst[9] = {NB, NA, NG, NA, NG, NB, NA, NB, NG};

struct EdgePtrs { const int* s[9]; const int* d[9]; };
struct FeatPtrs { const float* f[3]; };
struct Resid4 { const float4* f[3]; };

// ---------------- helpers ----------------
__device__ __forceinline__ uint32_t sw128(uint32_t o) { return o ^ ((o >> 3) & 0x70); }
// 128x128 bf16 tile: two [128 x 64] half-tiles of 16KB, 128B swizzled rows
__device__ __forceinline__ uint32_t toff128(uint32_t row, uint32_t k) {
    return ((k >> 6) << 14) + sw128(row * 128 + ((k & 63) << 1));
}
__device__ __forceinline__ uint32_t smem_u32(const void* p) {
    uint32_t a;
    asm("{ .reg .u64 t; cvta.to.shared.u64 t, %1; cvt.u32.u64 %0, t; }" : "=r"(a) : "l"(p));
    return a;
}
__device__ __forceinline__ void ldsm4(uint32_t& r0, uint32_t& r1, uint32_t& r2, uint32_t& r3,
                                      uint32_t addr) {
    asm volatile("ldmatrix.sync.aligned.m8n8.x4.shared.b16 {%0,%1,%2,%3}, [%4];"
                 : "=r"(r0), "=r"(r1), "=r"(r2), "=r"(r3) : "r"(addr));
}
__device__ __forceinline__ void mma_bf16(float* d, const uint32_t* a, uint32_t b0, uint32_t b1) {
    asm volatile(
        "mma.sync.aligned.m16n8k16.row.col.f32.bf16.bf16.f32 "
        "{%0,%1,%2,%3}, {%4,%5,%6,%7}, {%8,%9}, {%0,%1,%2,%3};"
        : "+f"(d[0]), "+f"(d[1]), "+f"(d[2]), "+f"(d[3])
        : "r"(a[0]), "r"(a[1]), "r"(a[2]), "r"(a[3]), "r"(b0), "r"(b1));
}
__device__ __forceinline__ void cpasync16(uint32_t dst, const void* src) {
    asm volatile("cp.async.ca.shared.global [%0], [%1], 16;" :: "r"(dst), "l"(src));
}
__device__ __forceinline__ __nv_bfloat162 pack_hi(float a, float b) {
    __nv_bfloat162 r; r.x = __float2bfloat16(a); r.y = __float2bfloat16(b); return r;
}

// ---------------- setup kernels ----------------
__global__ void k_zero3(int4* a, int4* b, int4* c, int n4) {
    int i = blockIdx.x * blockDim.x + threadIdx.x;
    if (i < n4) {
        int4 z = make_int4(0, 0, 0, 0);
        a[i] = z; b[i] = z; c[i] = z;
    }
}

__global__ void k_counti_all(EdgePtrs E, int* __restrict__ od, int* __restrict__ id) {
    const int eoff[10] = EOFF_INIT;
    const int soff[10] = SOFF_INIT;
    const int doff[10] = DOFF_INIT;
    int e = blockIdx.x * blockDim.x + threadIdx.x;
    if (e >= NE_TOT) return;
    int rel = 0;
#pragma unroll
    for (int r = 1; r < 9; r++) if (e >= eoff[r]) rel = r;
    int le = e - eoff[rel];
    atomicAdd(&od[soff[rel] + E.s[rel][le]], 1);
    atomicAdd(&id[doff[rel] + E.d[rel][le]], 1);
}

// block-local exclusive scan of ideg + block sums; also computes ns, nd
__global__ void k_scan1(const int* __restrict__ ideg, const int* __restrict__ odeg,
                        int* __restrict__ out, int* __restrict__ bsum,
                        float* __restrict__ ns, float* __restrict__ nd, int n) {
    __shared__ int sh[1024];
    int gid = blockIdx.x * 1024 + threadIdx.x;
    int v = (gid < n) ? ideg[gid] : 0;
    if (gid < n) {
        int od = odeg[gid];
        ns[gid] = (od > 0) ? rsqrtf((float)od) : 0.f;
        nd[gid] = (v > 0) ? rsqrtf((float)v) : 0.f;
    }
    sh[threadIdx.x] = v;
    __syncthreads();
#pragma unroll
    for (int s = 1; s < 1024; s <<= 1) {
        int t = (threadIdx.x >= s) ? sh[threadIdx.x - s] : 0;
        __syncthreads();
        sh[threadIdx.x] += t;
        __syncthreads();
    }
    if (gid < n) out[gid] = sh[threadIdx.x] - v;
    if (threadIdx.x == 1023) bsum[blockIdx.x] = sh[1023];
}

__global__ void k_scan3(int* __restrict__ out, const int* __restrict__ bsum, int n) {
    int b = blockIdx.x;
    int partial = 0;
    for (int j = threadIdx.x; j < b; j += 1024) partial += bsum[j];
#pragma unroll
    for (int s = 16; s >= 1; s >>= 1) partial += __shfl_down_sync(0xffffffffu, partial, s);
    __shared__ int tot;
    if (threadIdx.x == 0) tot = 0;
    __syncthreads();
    if ((threadIdx.x & 31) == 0) atomicAdd(&tot, partial);
    __syncthreads();
    int gid = b * 1024 + threadIdx.x;
    if (gid < n) out[gid] += tot;
}

// batched CSR fill; first threads also zero BN stats for layer 0
__global__ void k_fill_all(EdgePtrs E, const float* __restrict__ ns,
                           const int* __restrict__ offs, int* __restrict__ cur) {
    const int eoff[10] = EOFF_INIT;
    const int soff[10] = SOFF_INIT;
    const int doff[10] = DOFF_INIT;
    int e = blockIdx.x * blockDim.x + threadIdx.x;
    if (e < 9 * 256) g_stats[e] = 0.f;
    if (e >= NE_TOT) return;
    int rel = 0;
#pragma unroll
    for (int r = 1; r < 9; r++) if (e >= eoff[r]) rel = r;
    int le = e - eoff[rel];
    int ss = E.s[rel][le];
    int dd = E.d[rel][le];
    int gslot = doff[rel] + dd;
    int pos = offs[gslot] + atomicAdd(&cur[gslot], 1);
    g_eidx[pos] = ss;
    g_ew[pos] = ns[soff[rel] + ss];
}

// split W (fp32 [18][k][n]) into bf16 hi/lo stored as B tile [n][k], swizzled
__global__ void k_wsplit(const float* __restrict__ W) {
    int rel = blockIdx.x;  // 0..17
    const float* w = W + (size_t)rel * D * D;
    char* wh = (char*)g_wh + (size_t)rel * D * D * 2;
    char* wl = (char*)g_wl + (size_t)rel * D * D * 2;
    for (int idx = threadIdx.x; idx < D * D; idx += blockDim.x) {
        int k = idx >> 7, n = idx & 127;
        float x = w[idx];
        __nv_bfloat16 h = __float2bfloat16(x);
        __nv_bfloat16 l = __float2bfloat16(x - __bfloat162float(h));
        uint32_t off = toff128(n, k);
        *(__nv_bfloat16*)(wh + off) = h;
        *(__nv_bfloat16*)(wl + off) = l;
    }
}

// ---------------- fused gather + convert + GEMM + stats ----------------
// Per CTA: 128 dst rows of one relation. Gather rows from feat via CSR (nd folded),
// convert to bf16 hi/lo directly into swizzled smem tiles, 3-term mma.sync GEMM,
// write gout + column stats. A-tiles never touch global memory.
#define OFF_AHI  0
#define OFF_ALO  32768
#define OFF_BHI  65536
#define OFF_BLO  98304
#define OFF_STAT 131072
#define SMEM_DYN (131072 + 1024 + 1024)

__global__ __launch_bounds__(256, 1)
void k_fused_gemm(FeatPtrs F,
                  const int* __restrict__ offs, const int* __restrict__ ideg,
                  const int* __restrict__ eidx, const float* __restrict__ ew,
                  const float* __restrict__ nd,
                  const __nv_bfloat16* __restrict__ whAll,
                  const __nv_bfloat16* __restrict__ wlAll,
                  int layer, float* __restrict__ out, float* __restrict__ stats) {
    const int tbase[10] = TBASE_INIT;
    const int doff[10] = DOFF_INIT;
    const int st[9] = ST_INIT;
    extern __shared__ char smem_raw[];
    char* smem = (char*)((((uintptr_t)smem_raw) + 1023) & ~(uintptr_t)1023);
    uint32_t sa = smem_u32(smem);
    int tid = threadIdx.x;
    int lane = tid & 31;
    int wid = tid >> 5;
    int bid = blockIdx.x;

    int rel = 0;
#pragma unroll
    for (int r = 1; r < 9; r++) if (bid >= tbase[r]) rel = r;
    int rowBase = (bid - tbase[rel]) * 128;
    int ndst = doff[rel + 1] - doff[rel];
    int goutBase = doff[rel];
    const float* feat = F.f[st[rel]];

    // prefetch B hi/lo (this rel's W) via cp.async
    {
        int lr = layer * 9 + rel;
        const char* sBh = (const char*)whAll + (size_t)lr * 32768;
        const char* sBl = (const char*)wlAll + (size_t)lr * 32768;
#pragma unroll
        for (int i = tid; i < 2048; i += 256) {
            cpasync16(sa + OFF_BHI + i * 16, sBh + i * 16);
            cpasync16(sa + OFF_BLO + i * 16, sBl + i * 16);
        }
        asm volatile("cp.async.commit_group;" ::: "memory");
    }
    ((float*)(smem + OFF_STAT))[tid] = 0.f;

    // gather: warp handles rows wid, wid+8, ..., wid+120
    char* ah = smem + OFF_AHI;
    char* al = smem + OFF_ALO;
#pragma unroll 1
    for (int it = 0; it < 16; it++) {
        int lrow = it * 8 + wid;
        int grow = rowBase + lrow;
        float4 acc = make_float4(0.f, 0.f, 0.f, 0.f);
        if (grow < ndst) {
            int gslot = goutBase + grow;
            int o = __ldg(offs + gslot);
            int dg = __ldg(ideg + gslot);
            int e = 0;
            for (; e + 2 <= dg; e += 2) {
                int s0 = __ldg(eidx + o + e);
                int s1 = __ldg(eidx + o + e + 1);
                float w0 = __ldg(ew + o + e);
                float w1 = __ldg(ew + o + e + 1);
                float4 v0 = __ldg((const float4*)(feat + (size_t)s0 * D + lane * 4));
                float4 v1 = __ldg((const float4*)(feat + (size_t)s1 * D + lane * 4));
                acc.x += v0.x * w0 + v1.x * w1;
                acc.y += v0.y * w0 + v1.y * w1;
                acc.z += v0.z * w0 + v1.z * w1;
                acc.w += v0.w * w0 + v1.w * w1;
            }
            if (e < dg) {
                int s0 = __ldg(eidx + o + e);
                float w0 = __ldg(ew + o + e);
                float4 v0 = __ldg((const float4*)(feat + (size_t)s0 * D + lane * 4));
                acc.x += v0.x * w0;
                acc.y += v0.y * w0;
                acc.z += v0.z * w0;
                acc.w += v0.w * w0;
            }
            float ndv = __ldg(nd + gslot);
            acc.x *= ndv; acc.y *= ndv; acc.z *= ndv; acc.w *= ndv;
        }
        __nv_bfloat162 h0 = pack_hi(acc.x, acc.y);
        __nv_bfloat162 h1 = pack_hi(acc.z, acc.w);
        __nv_bfloat162 l0 = pack_hi(acc.x - __bfloat162float(h0.x),
                                    acc.y - __bfloat162float(h0.y));
        __nv_bfloat162 l1 = pack_hi(acc.z - __bfloat162float(h1.x),
                                    acc.w - __bfloat162float(h1.y));
        uint32_t o0 = toff128(lrow, lane * 4);
        uint32_t o1 = toff128(lrow, lane * 4 + 2);
        *(__nv_bfloat162*)(ah + o0) = h0;
        *(__nv_bfloat162*)(ah + o1) = h1;
        *(__nv_bfloat162*)(al + o0) = l0;
        *(__nv_bfloat162*)(al + o1) = l1;
    }

    asm volatile("cp.async.wait_group 0;" ::: "memory");
    __syncthreads();

    // 3-term split GEMM
    float acc[16][4];
#pragma unroll
    for (int t = 0; t < 16; t++)
#pragma unroll
        for (int j = 0; j < 4; j++) acc[t][j] = 0.f;

    int m0 = wid * 16;
    uint32_t rowA = m0 + (lane & 15);
    uint32_t kA = (lane >> 4) << 3;
    uint32_t rowB = (lane & 7) + ((lane >> 4) << 3);
    uint32_t kB = ((lane >> 3) & 1) << 3;

    const uint32_t abase[3] = {sa + OFF_AHI, sa + OFF_AHI, sa + OFF_ALO};
    const uint32_t bbase[3] = {sa + OFF_BHI, sa + OFF_BLO, sa + OFF_BHI};

#pragma unroll
    for (int s = 0; s < 3; s++) {
        uint32_t ab = abase[s];
        uint32_t bb = bbase[s];
#pragma unroll
        for (int k0 = 0; k0 < 128; k0 += 16) {
            uint32_t a[4];
            ldsm4(a[0], a[1], a[2], a[3], ab + toff128(rowA, k0 + kA));
#pragma unroll
            for (int nn = 0; nn < 8; nn++) {
                uint32_t b0, b1, b2, b3;
                ldsm4(b0, b1, b2, b3, bb + toff128(nn * 16 + rowB, k0 + kB));
                mma_bf16(acc[2 * nn], a, b0, b1);
                mma_bf16(acc[2 * nn + 1], a, b2, b3);
            }
        }
    }

    // epilogue: write gout (pre-BN, nd folded) + column stats
    int quad = lane >> 2;
    int cp = (lane & 3) * 2;
    int lr0 = rowBase + m0 + quad;
    int lr1 = lr0 + 8;
    bool v0 = lr0 < ndst, v1 = lr1 < ndst;
    float* sstat = (float*)(smem + OFF_STAT);

#pragma unroll
    for (int t = 0; t < 16; t++) {
        int c = t * 8 + cp;
        float x0 = acc[t][0], x1 = acc[t][1];
        float y0 = acc[t][2], y1 = acc[t][3];
        if (v0) *(float2*)(out + (size_t)(goutBase + lr0) * D + c) = make_float2(x0, x1);
        if (v1) *(float2*)(out + (size_t)(goutBase + lr1) * D + c) = make_float2(y0, y1);
        float s0 = (v0 ? x0 : 0.f) + (v1 ? y0 : 0.f);
        float s1 = (v0 ? x1 : 0.f) + (v1 ? y1 : 0.f);
        float q0 = (v0 ? x0 * x0 : 0.f) + (v1 ? y0 * y0 : 0.f);
        float q1 = (v0 ? x1 * x1 : 0.f) + (v1 ? y1 * y1 : 0.f);
#pragma unroll
        for (int S = 4; S <= 16; S <<= 1) {
            s0 += __shfl_xor_sync(0xffffffffu, s0, S);
            s1 += __shfl_xor_sync(0xffffffffu, s1, S);
            q0 += __shfl_xor_sync(0xffffffffu, q0, S);
            q1 += __shfl_xor_sync(0xffffffffu, q1, S);
        }
        if (lane < 4) {
            atomicAdd(&sstat[c], s0);
            atomicAdd(&sstat[c + 1], s1);
            atomicAdd(&sstat[128 + c], q0);
            atomicAdd(&sstat[128 + c + 1], q1);
        }
    }
    __syncthreads();
    atomicAdd(&stats[rel * 256 + tid], sstat[tid]);
}

// per-rel BN scale/shift from stats; re-zero stats for the next layer
__global__ void k_finalize9(const float* __restrict__ gammaL, const float* __restrict__ betaL) {
    int r = blockIdx.x;
    int c = threadIdx.x;
    float n = (float)d_ndst[r];
    float mu = g_stats[r * 256 + c] / n;
    float var = g_stats[r * 256 + 128 + c] / n - mu * mu;
    float inv = rsqrtf(var + BN_EPS);
    float sc = inv * gammaL[r * D + c];
    g_scale[r * D + c] = sc;
    g_shift[r * D + c] = betaL[r * D + c] - mu * sc;
    g_stats[r * 256 + c] = 0.f;
    g_stats[r * 256 + 128 + c] = 0.f;
}

// batched fused normalize + 3-rel sum (+ residual on layer 1)
__global__ void k_fuse_all(const float* __restrict__ gout, Resid4 R, int layer,
                           float4* __restrict__ out) {
    const int doff[10] = DOFF_INIT;
    int i = blockIdx.x * blockDim.x + threadIdx.x;
    if (i >= NTOT * 32) return;
    int row = i >> 5;
    int c4 = i & 31;
    int c = c4 * 4;
    int type = (row < NA) ? 0 : (row < NA + NB) ? 1 : 2;
    const int toff_[3] = {0, NA, NA + NB};
    const int rl_[3][3] = {{1, 3, 6}, {0, 5, 7}, {2, 4, 8}};
    int local = row - toff_[type];
    int r0 = rl_[type][0], r1 = rl_[type][1], r2 = rl_[type][2];
    const float4* g0 = (const float4*)(gout + (size_t)(doff[r0] + local) * D);
    const float4* g1 = (const float4*)(gout + (size_t)(doff[r1] + local) * D);
    const float4* g2 = (const float4*)(gout + (size_t)(doff[r2] + local) * D);
    float4 a = g0[c4], b = g1[c4], g = g2[c4];
    float4 o;
    o.x = a.x * g_scale[r0 * D + c + 0] + b.x * g_scale[r1 * D + c + 0] + g.x * g_scale[r2 * D + c + 0]
        + g_shift[r0 * D + c + 0] + g_shift[r1 * D + c + 0] + g_shift[r2 * D + c + 0];
    o.y = a.y * g_scale[r0 * D + c + 1] + b.y * g_scale[r1 * D + c + 1] + g.y * g_scale[r2 * D + c + 1]
        + g_shift[r0 * D + c + 1] + g_shift[r1 * D + c + 1] + g_shift[r2 * D + c + 1];
    o.z = a.z * g_scale[r0 * D + c + 2] + b.z * g_scale[r1 * D + c + 2] + g.z * g_scale[r2 * D + c + 2]
        + g_shift[r0 * D + c + 2] + g_shift[r1 * D + c + 2] + g_shift[r2 * D + c + 2];
    o.w = a.w * g_scale[r0 * D + c + 3] + b.w * g_scale[r1 * D + c + 3] + g.w * g_scale[r2 * D + c + 3]
        + g_shift[r0 * D + c + 3] + g_shift[r1 * D + c + 3] + g_shift[r2 * D + c + 3];
    if (layer == 1) {
        float4 rr = R.f[type][(size_t)local * 32 + c4];
        o.x += rr.x; o.y += rr.y; o.z += rr.z; o.w += rr.w;
    }
    out[i] = o;
}

// ---------------- host orchestration ----------------
static inline int cdiv(int a, int b) { return (a + b - 1) / b; }

extern "C" void kernel_launch(void* const* d_in, const int* in_sizes, int n_in,
                              void* d_out, int out_size) {
    const float* fa = (const float*)d_in[0];
    const float* fb = (const float*)d_in[1];
    const float* fg = (const float*)d_in[2];
    const float* W = (const float*)d_in[3];
    const float* gamma = (const float*)d_in[5];
    const float* beta = (const float*)d_in[6];

    EdgePtrs E;
    for (int r = 0; r < 9; r++) {
        E.s[r] = (const int*)d_in[7 + 2 * r];
        E.d[r] = (const int*)d_in[8 + 2 * r];
    }

    int *p_odeg, *p_ideg, *p_offs, *p_cursor, *p_bsum, *p_eidx;
    float *p_ns, *p_nd, *p_gout, *p_feat, *p_stats, *p_ew;
    __nv_bfloat16 *p_wh, *p_wl;
    cudaGetSymbolAddress((void**)&p_odeg, g_odeg);
    cudaGetSymbolAddress((void**)&p_ideg, g_ideg);
    cudaGetSymbolAddress((void**)&p_offs, g_offs);
    cudaGetSymbolAddress((void**)&p_cursor, g_cursor);
    cudaGetSymbolAddress((void**)&p_bsum, g_bsum);
    cudaGetSymbolAddress((void**)&p_eidx, g_eidx);
    cudaGetSymbolAddress((void**)&p_ew, g_ew);
    cudaGetSymbolAddress((void**)&p_ns, g_ns);
    cudaGetSymbolAddress((void**)&p_nd, g_nd);
    cudaGetSymbolAddress((void**)&p_gout, g_gout);
    cudaGetSymbolAddress((void**)&p_feat, g_feat);
    cudaGetSymbolAddress((void**)&p_stats, g_stats);
    cudaGetSymbolAddress((void**)&p_wh, g_wh);
    cudaGetSymbolAddress((void**)&p_wl, g_wl);

    cudaFuncSetAttribute(k_fused_gemm, cudaFuncAttributeMaxDynamicSharedMemorySize, SMEM_DYN);

    const int TB = 256;

    k_zero3<<<cdiv(DEG_TOT / 4, TB), TB>>>((int4*)p_odeg, (int4*)p_ideg, (int4*)p_cursor,
                                           DEG_TOT / 4);
    k_counti_all<<<cdiv(NE_TOT, TB), TB>>>(E, p_odeg, p_ideg);
    k_scan1<<<SCAN_NB, 1024>>>(p_ideg, p_odeg, p_offs, p_bsum, p_ns, p_nd, DEG_TOT);
    k_scan3<<<SCAN_NB, 1024>>>(p_offs, p_bsum, DEG_TOT);
    k_fill_all<<<cdiv(NE_TOT, TB), TB>>>(E, p_ns, p_offs, p_cursor);
    k_wsplit<<<18, 256>>>(W);

    FeatPtrs F0; F0.f[0] = fa; F0.f[1] = fb; F0.f[2] = fg;
    FeatPtrs F1; F1.f[0] = p_feat; F1.f[1] = p_feat + (size_t)NA * D;
    F1.f[2] = p_feat + (size_t)(NA + NB) * D;
    Resid4 R; R.f[0] = (const float4*)fa; R.f[1] = (const float4*)fb; R.f[2] = (const float4*)fg;

    // layer 0
    k_fused_gemm<<<NTILES, 256, SMEM_DYN>>>(F0, p_offs, p_ideg, p_eidx, p_ew, p_nd,
                                            p_wh, p_wl, 0, p_gout, p_stats);
    k_finalize9<<<9, 128>>>(gamma, beta);
    k_fuse_all<<<cdiv(NTOT * 32, TB), TB>>>(p_gout, R, 0, (float4*)p_feat);

    // layer 1
    k_fused_gemm<<<NTILES, 256, SMEM_DYN>>>(F1, p_offs, p_ideg, p_eidx, p_ew, p_nd,
                                            p_wh, p_wl, 1, p_gout, p_stats);
    k_finalize9<<<9, 128>>>(gamma + 9 * D, beta + 9 * D);
    k_fuse_all<<<cdiv(NTOT * 32, TB), TB>>>(p_gout, R, 1, (float4*)d_out);
}

// round 7
// speedup vs baseline: 1.0495x; 1.0495x over previous
#include <cuda_runtime.h>
#include <cuda_bf16.h>
#include <cstdint>

#define D 128
#define NA 100000
#define NB 150000
#define NG 2000
#define NTOT (NA + NB + NG)      // 252000
#define DEG_TOT 756000
#define NE_TOT 1352000
#define NTILES 5910
#define BN_EPS 1e-5f
#define SCAN_NB ((DEG_TOT + 1023) / 1024)   // 739

#define DOFF_INIT {0,150000,250000,252000,352000,354000,504000,604000,754000,756000}
#define SOFF_INIT {0,100000,250000,350000,352000,502000,504000,604000,754000,756000}
#define EOFF_INIT {0,300000,600000,700000,800000,950000,1100000,1200000,1350000,1352000}
#define TBASE_INIT {0,1172,1954,1970,2752,2768,3940,4722,5894,5910}
#define ST_INIT {0,1,0,2,1,2,0,1,2}

// ---------------- device scratch (zero-init at load; cleanup kernel re-zeroes) ----
__device__ int g_odeg[DEG_TOT];                   // MUST be zero at entry of each call
__device__ int g_ideg[DEG_TOT];                   // MUST be zero at entry of each call
__device__ int g_offs[DEG_TOT];                   // block-local exclusive scan
__device__ int g_offs2[DEG_TOT];                  // final global CSR offsets (deg>0 slots)
__device__ int g_cursor[DEG_TOT];                 // zeroed by scan1; == deg after fill
__device__ int g_bsum[SCAN_NB];
__device__ int2 g_epack[NE_TOT];                  // {src, ns_bits}
__device__ float g_ns[DEG_TOT];
__device__ float g_nd[DEG_TOT];
__device__ __align__(128) __nv_bfloat16 g_mh[(size_t)NTILES * 16384];  // A tiles hi
__device__ __align__(128) __nv_bfloat16 g_ml[(size_t)NTILES * 16384];  // A tiles lo
__device__ float g_gout[(size_t)DEG_TOT * D];
__device__ float g_feat[(size_t)NTOT * D];
__device__ float g_stats[9 * 2 * D];
__device__ float g_scale[9 * D];
__device__ float g_shift[9 * D];
__device__ __align__(128) __nv_bfloat16 g_wh[18 * D * D];
__device__ __align__(128) __nv_bfloat16 g_wl[18 * D * D];

__device__ const int d_ndst[9] = {NB, NA, NG, NA, NG, NB, NA, NB, NG};

struct EdgePtrs { const int* s[9]; const int* d[9]; };
struct FeatPtrs { const float* f[3]; };
struct Resid4 { const float4* f[3]; };

// ---------------- helpers ----------------
__device__ __forceinline__ uint32_t sw128(uint32_t o) { return o ^ ((o >> 3) & 0x70); }
__device__ __forceinline__ uint32_t toff128(uint32_t row, uint32_t k) {
    return ((k >> 6) << 14) + sw128(row * 128 + ((k & 63) << 1));
}
__device__ __forceinline__ uint32_t smem_u32(const void* p) {
    uint32_t a;
    asm("{ .reg .u64 t; cvta.to.shared.u64 t, %1; cvt.u32.u64 %0, t; }" : "=r"(a) : "l"(p));
    return a;
}
__device__ __forceinline__ void ldsm4(uint32_t& r0, uint32_t& r1, uint32_t& r2, uint32_t& r3,
                                      uint32_t addr) {
    asm volatile("ldmatrix.sync.aligned.m8n8.x4.shared.b16 {%0,%1,%2,%3}, [%4];"
                 : "=r"(r0), "=r"(r1), "=r"(r2), "=r"(r3) : "r"(addr));
}
__device__ __forceinline__ void mma_bf16(float* d, const uint32_t* a, uint32_t b0, uint32_t b1) {
    asm volatile(
        "mma.sync.aligned.m16n8k16.row.col.f32.bf16.bf16.f32 "
        "{%0,%1,%2,%3}, {%4,%5,%6,%7}, {%8,%9}, {%0,%1,%2,%3};"
        : "+f"(d[0]), "+f"(d[1]), "+f"(d[2]), "+f"(d[3])
        : "r"(a[0]), "r"(a[1]), "r"(a[2]), "r"(a[3]), "r"(b0), "r"(b1));
}
__device__ __forceinline__ void cpasync16(uint32_t dst, const void* src) {
    asm volatile("cp.async.ca.shared.global [%0], [%1], 16;" :: "r"(dst), "l"(src));
}
__device__ __forceinline__ __nv_bfloat162 pack_hi(float a, float b) {
    __nv_bfloat162 r; r.x = __float2bfloat16(a); r.y = __float2bfloat16(b); return r;
}

// ---------------- launch 0: count degrees + weight split ----------------
__global__ void k_prep(EdgePtrs E, const float* __restrict__ W) {
    if (blockIdx.x < 18) {
        int rel = blockIdx.x;
        const float* w = W + (size_t)rel * D * D;
        char* wh = (char*)g_wh + (size_t)rel * D * D * 2;
        char* wl = (char*)g_wl + (size_t)rel * D * D * 2;
        for (int idx = threadIdx.x; idx < D * D; idx += blockDim.x) {
            int k = idx >> 7, n = idx & 127;
            float x = w[idx];
            __nv_bfloat16 h = __float2bfloat16(x);
            __nv_bfloat16 l = __float2bfloat16(x - __bfloat162float(h));
            uint32_t off = toff128(n, k);
            *(__nv_bfloat16*)(wh + off) = h;
            *(__nv_bfloat16*)(wl + off) = l;
        }
        return;
    }
    const int eoff[10] = EOFF_INIT;
    const int soff[10] = SOFF_INIT;
    const int doff[10] = DOFF_INIT;
    int e = (blockIdx.x - 18) * blockDim.x + threadIdx.x;
    if (e >= NE_TOT) return;
    int rel = 0;
#pragma unroll
    for (int r = 1; r < 9; r++) if (e >= eoff[r]) rel = r;
    int le = e - eoff[rel];
    atomicAdd(&g_odeg[soff[rel] + E.s[rel][le]], 1);
    atomicAdd(&g_ideg[doff[rel] + E.d[rel][le]], 1);
}

// ---------------- launch 1: block-local scan + ns/nd + cursor/stats zero -------
__global__ void k_scan1() {
    int tid = threadIdx.x;
    int gid = blockIdx.x * 1024 + tid;
    int lane = tid & 31;
    int w = tid >> 5;
    int v = (gid < DEG_TOT) ? g_ideg[gid] : 0;
    if (gid < DEG_TOT) {
        int od = g_odeg[gid];
        g_ns[gid] = (od > 0) ? rsqrtf((float)od) : 0.f;
        g_nd[gid] = (v > 0) ? rsqrtf((float)v) : 0.f;
        g_cursor[gid] = 0;
    }
    if (blockIdx.x == 0) {
        for (int i = tid; i < 9 * 256; i += 1024) g_stats[i] = 0.f;
    }
    // warp inclusive scan
    int inc = v;
#pragma unroll
    for (int s = 1; s < 32; s <<= 1) {
        int x = __shfl_up_sync(0xffffffffu, inc, s);
        if (lane >= s) inc += x;
    }
    __shared__ int wsum[32];
    if (lane == 31) wsum[w] = inc;
    __syncthreads();
    if (w == 0) {
        int x = (lane < 32) ? wsum[lane] : 0;
        int sc = x;
#pragma unroll
        for (int s = 1; s < 32; s <<= 1) {
            int y = __shfl_up_sync(0xffffffffu, sc, s);
            if (lane >= s) sc += y;
        }
        wsum[lane] = sc - x;   // exclusive warp prefix
    }
    __syncthreads();
    int excl = inc - v + wsum[w];
    if (gid < DEG_TOT) g_offs[gid] = excl;
    if (tid == 1023) g_bsum[blockIdx.x] = excl + v;
}

// ---------------- launch 2: CSR fill (reconstructs block prefix in smem) -------
__global__ __launch_bounds__(256)
void k_fill_all(EdgePtrs E) {
    const int eoff[10] = EOFF_INIT;
    const int soff[10] = SOFF_INIT;
    const int doff[10] = DOFF_INIT;
    __shared__ int sb[768];
    __shared__ int wsum[8];
    int t = threadIdx.x;
    int base = t * 3;
    int a0 = (base < SCAN_NB) ? g_bsum[base] : 0;
    int a1 = (base + 1 < SCAN_NB) ? g_bsum[base + 1] : 0;
    int a2 = (base + 2 < SCAN_NB) ? g_bsum[base + 2] : 0;
    int tsum = a0 + a1 + a2;
    int lane = t & 31;
    int inc = tsum;
#pragma unroll
    for (int s = 1; s < 32; s <<= 1) {
        int x = __shfl_up_sync(0xffffffffu, inc, s);
        if (lane >= s) inc += x;
    }
    if (lane == 31) wsum[t >> 5] = inc;
    __syncthreads();
    if (t < 8) {
        int x = wsum[t];
        int sc = x;
#pragma unroll
        for (int s = 1; s < 8; s <<= 1) {
            int y = __shfl_up_sync(0xffu, sc, s);
            if (t >= s) sc += y;
        }
        wsum[t] = sc - x;
    }
    __syncthreads();
    int excl = inc - tsum + wsum[t >> 5];
    sb[base] = excl;
    sb[base + 1] = excl + a0;
    sb[base + 2] = excl + a0 + a1;
    __syncthreads();

    int e = blockIdx.x * blockDim.x + t;
    if (e >= NE_TOT) return;
    int rel = 0;
#pragma unroll
    for (int r = 1; r < 9; r++) if (e >= eoff[r]) rel = r;
    int le = e - eoff[rel];
    int ss = E.s[rel][le];
    int dd = E.d[rel][le];
    int gslot = doff[rel] + dd;
    int ofin = g_offs[gslot] + sb[gslot >> 10];
    int pos = ofin + atomicAdd(&g_cursor[gslot], 1);
    g_epack[pos] = make_int2(ss, __float_as_int(g_ns[soff[rel] + ss]));
    g_offs2[gslot] = ofin;
}

// ---------------- launch 3/7: batched gather -> swizzled bf16 hi/lo tiles -------
__global__ void k_gather_all(FeatPtrs F) {
    const int doff[10] = DOFF_INIT;
    const int tbase[10] = TBASE_INIT;
    const int st[9] = ST_INIT;
    int row = blockIdx.x * (blockDim.x >> 5) + (threadIdx.x >> 5);
    int lane = threadIdx.x & 31;
    if (row >= DEG_TOT) return;
    int rel = 0;
#pragma unroll
    for (int r = 1; r < 9; r++) if (row >= doff[r]) rel = r;
    int lrow = row - doff[rel];
    const float* feat = F.f[st[rel]];

    int dg = __ldg(g_cursor + row);          // == in-degree after fill
    float4 acc = make_float4(0.f, 0.f, 0.f, 0.f);
    if (dg > 0) {
        int o = __ldg(g_offs2 + row);
        const int2* ep = g_epack + o;
        int e = 0;
        for (; e + 2 <= dg; e += 2) {
            int2 p0 = __ldg(ep + e);
            int2 p1 = __ldg(ep + e + 1);
            float w0 = __int_as_float(p0.y);
            float w1 = __int_as_float(p1.y);
            float4 v0 = __ldg((const float4*)(feat + (size_t)p0.x * D + lane * 4));
            float4 v1 = __ldg((const float4*)(feat + (size_t)p1.x * D + lane * 4));
            acc.x += v0.x * w0 + v1.x * w1;
            acc.y += v0.y * w0 + v1.y * w1;
            acc.z += v0.z * w0 + v1.z * w1;
            acc.w += v0.w * w0 + v1.w * w1;
        }
        if (e < dg) {
            int2 p0 = __ldg(ep + e);
            float w0 = __int_as_float(p0.y);
            float4 v0 = __ldg((const float4*)(feat + (size_t)p0.x * D + lane * 4));
            acc.x += v0.x * w0;
            acc.y += v0.y * w0;
            acc.z += v0.z * w0;
            acc.w += v0.w * w0;
        }
        float ndv = __ldg(g_nd + row);
        acc.x *= ndv; acc.y *= ndv; acc.z *= ndv; acc.w *= ndv;
    }

    __nv_bfloat162 h0 = pack_hi(acc.x, acc.y);
    __nv_bfloat162 h1 = pack_hi(acc.z, acc.w);
    __nv_bfloat162 l0 = pack_hi(acc.x - __bfloat162float(h0.x), acc.y - __bfloat162float(h0.y));
    __nv_bfloat162 l1 = pack_hi(acc.z - __bfloat162float(h1.x), acc.w - __bfloat162float(h1.y));

    size_t tile = (size_t)tbase[rel] + (lrow >> 7);
    int ir = lrow & 127;
    char* bh = (char*)g_mh + tile * 32768;
    char* bl = (char*)g_ml + tile * 32768;
    uint32_t o0 = toff128(ir, lane * 4);
    uint32_t o1 = toff128(ir, lane * 4 + 2);
    *(__nv_bfloat162*)(bh + o0) = h0;
    *(__nv_bfloat162*)(bh + o1) = h1;
    *(__nv_bfloat162*)(bl + o0) = l0;
    *(__nv_bfloat162*)(bl + o1) = l1;
}

// ---------------- batched GEMM + stats epilogue ----------------
#define OFF_AHI  0
#define OFF_ALO  32768
#define OFF_BHI  65536
#define OFF_BLO  98304
#define OFF_STAT 131072
#define SMEM_DYN (131072 + 1024 + 1024)

__global__ __launch_bounds__(256, 1)
void k_gemm_all(const __nv_bfloat16* __restrict__ mh, const __nv_bfloat16* __restrict__ ml,
                const __nv_bfloat16* __restrict__ whAll, const __nv_bfloat16* __restrict__ wlAll,
                int layer, float* __restrict__ out, float* __restrict__ stats) {
    const int tbase[10] = TBASE_INIT;
    const int doff[10] = DOFF_INIT;
    extern __shared__ char smem_raw[];
    char* smem = (char*)((((uintptr_t)smem_raw) + 1023) & ~(uintptr_t)1023);
    uint32_t sa = smem_u32(smem);
    int tid = threadIdx.x;
    int lane = tid & 31;
    int wid = tid >> 5;
    int bid = blockIdx.x;

    int rel = 0;
#pragma unroll
    for (int r = 1; r < 9; r++) if (bid >= tbase[r]) rel = r;
    int rowBase = (bid - tbase[rel]) * 128;
    int ndst = doff[rel + 1] - doff[rel];
    int goutBase = doff[rel];

    ((float*)(smem + OFF_STAT))[tid] = 0.f;
    {
        const char* sAh = (const char*)mh + (size_t)bid * 32768;
        const char* sAl = (const char*)ml + (size_t)bid * 32768;
        int lr = layer * 9 + rel;
        const char* sBh = (const char*)whAll + (size_t)lr * 32768;
        const char* sBl = (const char*)wlAll + (size_t)lr * 32768;
#pragma unroll
        for (int i = tid; i < 2048; i += 256) {
            cpasync16(sa + OFF_AHI + i * 16, sAh + i * 16);
            cpasync16(sa + OFF_ALO + i * 16, sAl + i * 16);
            cpasync16(sa + OFF_BHI + i * 16, sBh + i * 16);
            cpasync16(sa + OFF_BLO + i * 16, sBl + i * 16);
        }
        asm volatile("cp.async.commit_group;" ::: "memory");
        asm volatile("cp.async.wait_group 0;" ::: "memory");
    }
    __syncthreads();

    float acc[16][4];
#pragma unroll
    for (int t = 0; t < 16; t++)
#pragma unroll
        for (int j = 0; j < 4; j++) acc[t][j] = 0.f;

    int m0 = wid * 16;
    uint32_t rowA = m0 + (lane & 15);
    uint32_t kA = (lane >> 4) << 3;
    uint32_t rowB = (lane & 7) + ((lane >> 4) << 3);
    uint32_t kB = ((lane >> 3) & 1) << 3;

    const uint32_t abase[3] = {sa + OFF_AHI, sa + OFF_AHI, sa + OFF_ALO};
    const uint32_t bbase[3] = {sa + OFF_BHI, sa + OFF_BLO, sa + OFF_BHI};

#pragma unroll
    for (int s = 0; s < 3; s++) {
        uint32_t ab = abase[s];
        uint32_t bb = bbase[s];
#pragma unroll
        for (int k0 = 0; k0 < 128; k0 += 16) {
            uint32_t a[4];
            ldsm4(a[0], a[1], a[2], a[3], ab + toff128(rowA, k0 + kA));
#pragma unroll
            for (int nn = 0; nn < 8; nn++) {
                uint32_t b0, b1, b2, b3;
                ldsm4(b0, b1, b2, b3, bb + toff128(nn * 16 + rowB, k0 + kB));
                mma_bf16(acc[2 * nn], a, b0, b1);
                mma_bf16(acc[2 * nn + 1], a, b2, b3);
            }
        }
    }

    int quad = lane >> 2;
    int cp = (lane & 3) * 2;
    int lr0 = rowBase + m0 + quad;
    int lr1 = lr0 + 8;
    bool v0 = lr0 < ndst, v1 = lr1 < ndst;
    float* sstat = (float*)(smem + OFF_STAT);

#pragma unroll
    for (int t = 0; t < 16; t++) {
        int c = t * 8 + cp;
        float x0 = acc[t][0], x1 = acc[t][1];
        float y0 = acc[t][2], y1 = acc[t][3];
        if (v0) *(float2*)(out + (size_t)(goutBase + lr0) * D + c) = make_float2(x0, x1);
        if (v1) *(float2*)(out + (size_t)(goutBase + lr1) * D + c) = make_float2(y0, y1);
        float s0 = (v0 ? x0 : 0.f) + (v1 ? y0 : 0.f);
        float s1 = (v0 ? x1 : 0.f) + (v1 ? y1 : 0.f);
        float q0 = (v0 ? x0 * x0 : 0.f) + (v1 ? y0 * y0 : 0.f);
        float q1 = (v0 ? x1 * x1 : 0.f) + (v1 ? y1 * y1 : 0.f);
#pragma unroll
        for (int S = 4; S <= 16; S <<= 1) {
            s0 += __shfl_xor_sync(0xffffffffu, s0, S);
            s1 += __shfl_xor_sync(0xffffffffu, s1, S);
            q0 += __shfl_xor_sync(0xffffffffu, q0, S);
            q1 += __shfl_xor_sync(0xffffffffu, q1, S);
        }
        if (lane < 4) {
            atomicAdd(&sstat[c], s0);
            atomicAdd(&sstat[c + 1], s1);
            atomicAdd(&sstat[128 + c], q0);
            atomicAdd(&sstat[128 + c + 1], q1);
        }
    }
    __syncthreads();
    atomicAdd(&stats[rel * 256 + tid], sstat[tid]);
}

// ---------------- BN finalize (re-zeroes stats for next layer) ----------------
__global__ void k_finalize9(const float* __restrict__ gammaL, const float* __restrict__ betaL) {
    int r = blockIdx.x;
    int c = threadIdx.x;
    float n = (float)d_ndst[r];
    float mu = g_stats[r * 256 + c] / n;
    float var = g_stats[r * 256 + 128 + c] / n - mu * mu;
    float inv = rsqrtf(var + BN_EPS);
    float sc = inv * gammaL[r * D + c];
    g_scale[r * D + c] = sc;
    g_shift[r * D + c] = betaL[r * D + c] - mu * sc;
    g_stats[r * 256 + c] = 0.f;
    g_stats[r * 256 + 128 + c] = 0.f;
}

// ---------------- fused normalize + 3-rel sum (+ residual on layer 1) ----------
__global__ void k_fuse_all(const float* __restrict__ gout, Resid4 R, int layer,
                           float4* __restrict__ out) {
    const int doff[10] = DOFF_INIT;
    int i = blockIdx.x * blockDim.x + threadIdx.x;
    if (i >= NTOT * 32) return;
    int row = i >> 5;
    int c4 = i & 31;
    int c = c4 * 4;
    int type = (row < NA) ? 0 : (row < NA + NB) ? 1 : 2;
    const int toff_[3] = {0, NA, NA + NB};
    const int rl_[3][3] = {{1, 3, 6}, {0, 5, 7}, {2, 4, 8}};
    int local = row - toff_[type];
    int r0 = rl_[type][0], r1 = rl_[type][1], r2 = rl_[type][2];
    float4 a = ((const float4*)(gout + (size_t)(doff[r0] + local) * D))[c4];
    float4 b = ((const float4*)(gout + (size_t)(doff[r1] + local) * D))[c4];
    float4 g = ((const float4*)(gout + (size_t)(doff[r2] + local) * D))[c4];
    float4 o;
    o.x = a.x * g_scale[r0 * D + c + 0] + b.x * g_scale[r1 * D + c + 0] + g.x * g_scale[r2 * D + c + 0]
        + g_shift[r0 * D + c + 0] + g_shift[r1 * D + c + 0] + g_shift[r2 * D + c + 0];
    o.y = a.y * g_scale[r0 * D + c + 1] + b.y * g_scale[r1 * D + c + 1] + g.y * g_scale[r2 * D + c + 1]
        + g_shift[r0 * D + c + 1] + g_shift[r1 * D + c + 1] + g_shift[r2 * D + c + 1];
    o.z = a.z * g_scale[r0 * D + c + 2] + b.z * g_scale[r1 * D + c + 2] + g.z * g_scale[r2 * D + c + 2]
        + g_shift[r0 * D + c + 2] + g_shift[r1 * D + c + 2] + g_shift[r2 * D + c + 2];
    o.w = a.w * g_scale[r0 * D + c + 3] + b.w * g_scale[r1 * D + c + 3] + g.w * g_scale[r2 * D + c + 3]
        + g_shift[r0 * D + c + 3] + g_shift[r1 * D + c + 3] + g_shift[r2 * D + c + 3];
    if (layer == 1) {
        float4 rr = R.f[type][(size_t)local * 32 + c4];
        o.x += rr.x; o.y += rr.y; o.z += rr.z; o.w += rr.w;
    }
    out[i] = o;
}

// ---------------- final cleanup: restore zero-state for next call ----------------
__global__ void k_cleanup() {
    int i = blockIdx.x * blockDim.x + threadIdx.x;
    int n4 = DEG_TOT / 4;
    if (i < n4) {
        ((int4*)g_odeg)[i] = make_int4(0, 0, 0, 0);
        ((int4*)g_ideg)[i] = make_int4(0, 0, 0, 0);
    }
}

// ---------------- host orchestration ----------------
static inline int cdiv(int a, int b) { return (a + b - 1) / b; }

extern "C" void kernel_launch(void* const* d_in, const int* in_sizes, int n_in,
                              void* d_out, int out_size) {
    const float* fa = (const float*)d_in[0];
    const float* fb = (const float*)d_in[1];
    const float* fg = (const float*)d_in[2];
    const float* W = (const float*)d_in[3];
    const float* gamma = (const float*)d_in[5];
    const float* beta = (const float*)d_in[6];

    EdgePtrs E;
    for (int r = 0; r < 9; r++) {
        E.s[r] = (const int*)d_in[7 + 2 * r];
        E.d[r] = (const int*)d_in[8 + 2 * r];
    }

    float *p_gout, *p_feat, *p_stats;
    __nv_bfloat16 *p_wh, *p_wl, *p_mh, *p_ml;
    cudaGetSymbolAddress((void**)&p_gout, g_gout);
    cudaGetSymbolAddress((void**)&p_feat, g_feat);
    cudaGetSymbolAddress((void**)&p_stats, g_stats);
    cudaGetSymbolAddress((void**)&p_wh, g_wh);
    cudaGetSymbolAddress((void**)&p_wl, g_wl);
    cudaGetSymbolAddress((void**)&p_mh, g_mh);
    cudaGetSymbolAddress((void**)&p_ml, g_ml);

    cudaFuncSetAttribute(k_gemm_all, cudaFuncAttributeMaxDynamicSharedMemorySize, SMEM_DYN);

    const int TB = 256;

    FeatPtrs F0; F0.f[0] = fa; F0.f[1] = fb; F0.f[2] = fg;
    FeatPtrs F1; F1.f[0] = p_feat; F1.f[1] = p_feat + (size_t)NA * D;
    F1.f[2] = p_feat + (size_t)(NA + NB) * D;
    Resid4 R; R.f[0] = (const float4*)fa; R.f[1] = (const float4*)fb; R.f[2] = (const float4*)fg;

    // 0: count degrees + weight split (odeg/ideg zeroed by static init / cleanup)
    k_prep<<<18 + cdiv(NE_TOT, TB), TB>>>(E, W);
    // 1: block-local scan + ns/nd + cursor/stats zero
    k_scan1<<<SCAN_NB, 1024>>>();
    // 2: CSR fill (writes final offsets + packed edges)
    k_fill_all<<<cdiv(NE_TOT, TB), TB>>>(E);
    // 3: gather L0  <-- ncu profiles this launch
    k_gather_all<<<cdiv(DEG_TOT, TB / 32), TB>>>(F0);
    // 4: GEMM L0
    k_gemm_all<<<NTILES, 256, SMEM_DYN>>>(p_mh, p_ml, p_wh, p_wl, 0, p_gout, p_stats);
    // 5: finalize L0
    k_finalize9<<<9, 128>>>(gamma, beta);
    // 6: fuse L0 -> g_feat
    k_fuse_all<<<cdiv(NTOT * 32, TB), TB>>>(p_gout, R, 0, (float4*)p_feat);
    // 7-10: layer 1
    k_gather_all<<<cdiv(DEG_TOT, TB / 32), TB>>>(F1);
    k_gemm_all<<<NTILES, 256, SMEM_DYN>>>(p_mh, p_ml, p_wh, p_wl, 1, p_gout, p_stats);
    k_finalize9<<<9, 128>>>(gamma + 9 * D, beta + 9 * D);
    k_fuse_all<<<cdiv(NTOT * 32, TB), TB>>>(p_gout, R, 1, (float4*)d_out);
    // 11: restore zero-state for next call
    k_cleanup<<<cdiv(DEG_TOT / 4, TB), TB>>>();
}

// round 8
// speedup vs baseline: 1.4365x; 1.3687x over previous
#include <cuda_runtime.h>
#include <cuda_fp16.h>
#include <cstdint>

#define D 128
#define NA 100000
#define NB 150000
#define NG 2000
#define NTOT (NA + NB + NG)      // 252000
#define DEG_TOT 756000
#define NE_TOT 1352000
#define NTILES 5910
#define BN_EPS 1e-5f
#define SCAN_NB ((DEG_TOT + 1023) / 1024)   // 739

#define DOFF_INIT {0,150000,250000,252000,352000,354000,504000,604000,754000,756000}
#define SOFF_INIT {0,100000,250000,350000,352000,502000,504000,604000,754000,756000}
#define EOFF_INIT {0,300000,600000,700000,800000,950000,1100000,1200000,1350000,1352000}
#define TBASE_INIT {0,1172,1954,1970,2752,2768,3940,4722,5894,5910}
#define ST_INIT {0,1,0,2,1,2,0,1,2}

#define EBLK ((NE_TOT + 255) / 256)          // 5282
#define CBLK ((NTOT * 32 + 255) / 256)       // 31500 (float4 units)

// ---------------- device scratch (zero-init at load; cleanup re-zeroes deg) ----
__device__ int g_odeg[DEG_TOT];                   // zero at entry (init / cleanup)
__device__ int g_ideg[DEG_TOT];                   // zero at entry
__device__ int g_offs[DEG_TOT];                   // block-local exclusive scan
__device__ int g_offs2[DEG_TOT];                  // final CSR offsets
__device__ int g_cursor[DEG_TOT];                 // zeroed by scan1; == deg after fill
__device__ int g_bsum[SCAN_NB];
__device__ int2 g_epack[NE_TOT];                  // {src, ns_bits}
__device__ float g_ns[DEG_TOT];
__device__ float g_nd[DEG_TOT];
__device__ __align__(128) __half g_fh[(size_t)NTOT * D];   // fp16 features (both layers)
__device__ __align__(128) __half g_mh[(size_t)NTILES * 16384];  // A tiles fp16 (swizzled)
__device__ float g_gout[(size_t)DEG_TOT * D];
__device__ float g_stats[9 * 2 * D];
__device__ float g_scale[9 * D];
__device__ float g_shift[9 * D];
__device__ __align__(128) __half g_wh[18 * D * D];   // W hi fp16, swizzled B layout
__device__ __align__(128) __half g_wl[18 * D * D];   // W lo fp16

__device__ const int d_ndst[9] = {NB, NA, NG, NA, NG, NB, NA, NB, NG};

struct EdgePtrs { const int* s[9]; const int* d[9]; };
struct Resid4 { const float4* f[3]; };
struct In3 { const float4* f[3]; };

// ---------------- helpers ----------------
__device__ __forceinline__ uint32_t sw128(uint32_t o) { return o ^ ((o >> 3) & 0x70); }
__device__ __forceinline__ uint32_t toff128(uint32_t row, uint32_t k) {
    return ((k >> 6) << 14) + sw128(row * 128 + ((k & 63) << 1));
}
__device__ __forceinline__ uint32_t smem_u32(const void* p) {
    uint32_t a;
    asm("{ .reg .u64 t; cvta.to.shared.u64 t, %1; cvt.u32.u64 %0, t; }" : "=r"(a) : "l"(p));
    return a;
}
__device__ __forceinline__ void ldsm4(uint32_t& r0, uint32_t& r1, uint32_t& r2, uint32_t& r3,
                                      uint32_t addr) {
    asm volatile("ldmatrix.sync.aligned.m8n8.x4.shared.b16 {%0,%1,%2,%3}, [%4];"
                 : "=r"(r0), "=r"(r1), "=r"(r2), "=r"(r3) : "r"(addr));
}
__device__ __forceinline__ void mma_f16(float* d, const uint32_t* a, uint32_t b0, uint32_t b1) {
    asm volatile(
        "mma.sync.aligned.m16n8k16.row.col.f32.f16.f16.f32 "
        "{%0,%1,%2,%3}, {%4,%5,%6,%7}, {%8,%9}, {%0,%1,%2,%3};"
        : "+f"(d[0]), "+f"(d[1]), "+f"(d[2]), "+f"(d[3])
        : "r"(a[0]), "r"(a[1]), "r"(a[2]), "r"(a[3]), "r"(b0), "r"(b1));
}
__device__ __forceinline__ void cpasync16(uint32_t dst, const void* src) {
    asm volatile("cp.async.ca.shared.global [%0], [%1], 16;" :: "r"(dst), "l"(src));
}

// ---------------- launch 0: W split (fp16 hi/lo) + degree count + feat->fp16 ----
__global__ void k_prep(EdgePtrs E, const float* __restrict__ W, In3 IN) {
    if (blockIdx.x < 18) {
        int rel = blockIdx.x;
        const float* w = W + (size_t)rel * D * D;
        char* wh = (char*)g_wh + (size_t)rel * D * D * 2;
        char* wl = (char*)g_wl + (size_t)rel * D * D * 2;
        for (int idx = threadIdx.x; idx < D * D; idx += blockDim.x) {
            int k = idx >> 7, n = idx & 127;
            float x = w[idx];
            __half h = __float2half_rn(x);
            __half l = __float2half_rn(x - __half2float(h));
            uint32_t off = toff128(n, k);
            *(__half*)(wh + off) = h;
            *(__half*)(wl + off) = l;
        }
        return;
    }
    if (blockIdx.x < 18 + EBLK) {
        const int eoff[10] = EOFF_INIT;
        const int soff[10] = SOFF_INIT;
        const int doff[10] = DOFF_INIT;
        int e = (blockIdx.x - 18) * blockDim.x + threadIdx.x;
        if (e >= NE_TOT) return;
        int rel = 0;
#pragma unroll
        for (int r = 1; r < 9; r++) if (e >= eoff[r]) rel = r;
        int le = e - eoff[rel];
        atomicAdd(&g_odeg[soff[rel] + E.s[rel][le]], 1);
        atomicAdd(&g_ideg[doff[rel] + E.d[rel][le]], 1);
        return;
    }
    // feat -> fp16 (float4 granularity)
    int i = (blockIdx.x - 18 - EBLK) * blockDim.x + threadIdx.x;
    if (i >= NTOT * 32) return;
    int t = (i < NA * 32) ? 0 : (i < (NA + NB) * 32) ? 1 : 2;
    const int base4[3] = {0, NA * 32, (NA + NB) * 32};
    float4 v = IN.f[t][i - base4[t]];
    __half2 h0 = __floats2half2_rn(v.x, v.y);
    __half2 h1 = __floats2half2_rn(v.z, v.w);
    ((__half2*)g_fh)[i * 2] = h0;
    ((__half2*)g_fh)[i * 2 + 1] = h1;
}

// ---------------- launch 1: block-local scan + ns/nd + cursor/stats zero -------
__global__ void k_scan1() {
    int tid = threadIdx.x;
    int gid = blockIdx.x * 1024 + tid;
    int lane = tid & 31;
    int w = tid >> 5;
    int v = (gid < DEG_TOT) ? g_ideg[gid] : 0;
    if (gid < DEG_TOT) {
        int od = g_odeg[gid];
        g_ns[gid] = (od > 0) ? rsqrtf((float)od) : 0.f;
        g_nd[gid] = (v > 0) ? rsqrtf((float)v) : 0.f;
        g_cursor[gid] = 0;
    }
    if (blockIdx.x == 0) {
        for (int i = tid; i < 9 * 256; i += 1024) g_stats[i] = 0.f;
    }
    int inc = v;
#pragma unroll
    for (int s = 1; s < 32; s <<= 1) {
        int x = __shfl_up_sync(0xffffffffu, inc, s);
        if (lane >= s) inc += x;
    }
    __shared__ int wsum[32];
    if (lane == 31) wsum[w] = inc;
    __syncthreads();
    if (w == 0) {
        int x = (lane < 32) ? wsum[lane] : 0;
        int sc = x;
#pragma unroll
        for (int s = 1; s < 32; s <<= 1) {
            int y = __shfl_up_sync(0xffffffffu, sc, s);
            if (lane >= s) sc += y;
        }
        wsum[lane] = sc - x;
    }
    __syncthreads();
    int excl = inc - v + wsum[w];
    if (gid < DEG_TOT) g_offs[gid] = excl;
    if (tid == 1023) g_bsum[blockIdx.x] = excl + v;
}

// ---------------- launch 2: CSR fill ----------------
__global__ __launch_bounds__(256)
void k_fill_all(EdgePtrs E) {
    const int eoff[10] = EOFF_INIT;
    const int soff[10] = SOFF_INIT;
    const int doff[10] = DOFF_INIT;
    __shared__ int sb[768];
    __shared__ int wsum[8];
    int t = threadIdx.x;
    int base = t * 3;
    int a0 = (base < SCAN_NB) ? g_bsum[base] : 0;
    int a1 = (base + 1 < SCAN_NB) ? g_bsum[base + 1] : 0;
    int a2 = (base + 2 < SCAN_NB) ? g_bsum[base + 2] : 0;
    int tsum = a0 + a1 + a2;
    int lane = t & 31;
    int inc = tsum;
#pragma unroll
    for (int s = 1; s < 32; s <<= 1) {
        int x = __shfl_up_sync(0xffffffffu, inc, s);
        if (lane >= s) inc += x;
    }
    if (lane == 31) wsum[t >> 5] = inc;
    __syncthreads();
    if (t < 8) {
        int x = wsum[t];
        int sc = x;
#pragma unroll
        for (int s = 1; s < 8; s <<= 1) {
            int y = __shfl_up_sync(0xffu, sc, s);
            if (t >= s) sc += y;
        }
        wsum[t] = sc - x;
    }
    __syncthreads();
    int excl = inc - tsum + wsum[t >> 5];
    sb[base] = excl;
    sb[base + 1] = excl + a0;
    sb[base + 2] = excl + a0 + a1;
    __syncthreads();

    int e = blockIdx.x * blockDim.x + t;
    if (e >= NE_TOT) return;
    int rel = 0;
#pragma unroll
    for (int r = 1; r < 9; r++) if (e >= eoff[r]) rel = r;
    int le = e - eoff[rel];
    int ss = E.s[rel][le];
    int dd = E.d[rel][le];
    int gslot = doff[rel] + dd;
    int ofin = g_offs[gslot] + sb[gslot >> 10];
    int pos = ofin + atomicAdd(&g_cursor[gslot], 1);
    g_epack[pos] = make_int2(ss, __float_as_int(g_ns[soff[rel] + ss]));
    g_offs2[gslot] = ofin;
}

// ---------------- gather: CSR sum of fp16 rows -> fp16 swizzled A tiles --------
__global__ void k_gather_all(const __half* __restrict__ fh) {
    const int doff[10] = DOFF_INIT;
    const int tbase[10] = TBASE_INIT;
    const int st[9] = ST_INIT;
    const int stoff[3] = {0, NA, NA + NB};
    int row = blockIdx.x * (blockDim.x >> 5) + (threadIdx.x >> 5);
    int lane = threadIdx.x & 31;
    if (row >= DEG_TOT) return;
    int rel = 0;
#pragma unroll
    for (int r = 1; r < 9; r++) if (row >= doff[r]) rel = r;
    int lrow = row - doff[rel];
    const __half* feat = fh + (size_t)stoff[st[rel]] * D;

    int dg = __ldg(g_cursor + row);
    float4 acc = make_float4(0.f, 0.f, 0.f, 0.f);
    if (dg > 0) {
        int o = __ldg(g_offs2 + row);
        const int2* ep = g_epack + o;
        int e = 0;
        for (; e + 2 <= dg; e += 2) {
            int2 p0 = __ldg(ep + e);
            int2 p1 = __ldg(ep + e + 1);
            float w0 = __int_as_float(p0.y);
            float w1 = __int_as_float(p1.y);
            uint2 hv0 = __ldg((const uint2*)(feat + (size_t)p0.x * D + lane * 4));
            uint2 hv1 = __ldg((const uint2*)(feat + (size_t)p1.x * D + lane * 4));
            float2 a0 = __half22float2(*(__half2*)&hv0.x);
            float2 a1 = __half22float2(*(__half2*)&hv0.y);
            float2 b0 = __half22float2(*(__half2*)&hv1.x);
            float2 b1 = __half22float2(*(__half2*)&hv1.y);
            acc.x += a0.x * w0 + b0.x * w1;
            acc.y += a0.y * w0 + b0.y * w1;
            acc.z += a1.x * w0 + b1.x * w1;
            acc.w += a1.y * w0 + b1.y * w1;
        }
        if (e < dg) {
            int2 p0 = __ldg(ep + e);
            float w0 = __int_as_float(p0.y);
            uint2 hv0 = __ldg((const uint2*)(feat + (size_t)p0.x * D + lane * 4));
            float2 a0 = __half22float2(*(__half2*)&hv0.x);
            float2 a1 = __half22float2(*(__half2*)&hv0.y);
            acc.x += a0.x * w0;
            acc.y += a0.y * w0;
            acc.z += a1.x * w0;
            acc.w += a1.y * w0;
        }
        float ndv = __ldg(g_nd + row);
        acc.x *= ndv; acc.y *= ndv; acc.z *= ndv; acc.w *= ndv;
    }

    __half2 h0 = __floats2half2_rn(acc.x, acc.y);
    __half2 h1 = __floats2half2_rn(acc.z, acc.w);
    size_t tile = (size_t)tbase[rel] + (lrow >> 7);
    int ir = lrow & 127;
    char* bh = (char*)g_mh + tile * 32768;
    *(__half2*)(bh + toff128(ir, lane * 4)) = h0;
    *(__half2*)(bh + toff128(ir, lane * 4 + 2)) = h1;
}

// ---------------- batched GEMM (2-product fp16 split) + stats epilogue ---------
#define OFF_A    0
#define OFF_BHI  32768
#define OFF_BLO  65536
#define OFF_STAT 98304
#define SMEM_DYN (98304 + 1024 + 1024)

__global__ __launch_bounds__(256, 2)
void k_gemm_all(const __half* __restrict__ mh,
                const __half* __restrict__ whAll, const __half* __restrict__ wlAll,
                int layer, float* __restrict__ out, float* __restrict__ stats) {
    const int tbase[10] = TBASE_INIT;
    const int doff[10] = DOFF_INIT;
    extern __shared__ char smem_raw[];
    char* smem = (char*)((((uintptr_t)smem_raw) + 1023) & ~(uintptr_t)1023);
    uint32_t sa = smem_u32(smem);
    int tid = threadIdx.x;
    int lane = tid & 31;
    int wid = tid >> 5;
    int bid = blockIdx.x;

    int rel = 0;
#pragma unroll
    for (int r = 1; r < 9; r++) if (bid >= tbase[r]) rel = r;
    int rowBase = (bid - tbase[rel]) * 128;
    int ndst = doff[rel + 1] - doff[rel];
    int goutBase = doff[rel];

    ((float*)(smem + OFF_STAT))[tid] = 0.f;
    {
        const char* sA = (const char*)mh + (size_t)bid * 32768;
        int lr = layer * 9 + rel;
        const char* sBh = (const char*)whAll + (size_t)lr * 32768;
        const char* sBl = (const char*)wlAll + (size_t)lr * 32768;
#pragma unroll
        for (int i = tid; i < 2048; i += 256) {
            cpasync16(sa + OFF_A + i * 16, sA + i * 16);
            cpasync16(sa + OFF_BHI + i * 16, sBh + i * 16);
            cpasync16(sa + OFF_BLO + i * 16, sBl + i * 16);
        }
        asm volatile("cp.async.commit_group;" ::: "memory");
        asm volatile("cp.async.wait_group 0;" ::: "memory");
    }
    __syncthreads();

    float acc[16][4];
#pragma unroll
    for (int t = 0; t < 16; t++)
#pragma unroll
        for (int j = 0; j < 4; j++) acc[t][j] = 0.f;

    int m0 = wid * 16;
    uint32_t rowA = m0 + (lane & 15);
    uint32_t kA = (lane >> 4) << 3;
    uint32_t rowB = (lane & 7) + ((lane >> 4) << 3);
    uint32_t kB = ((lane >> 3) & 1) << 3;

    const uint32_t bbase[2] = {sa + OFF_BHI, sa + OFF_BLO};

#pragma unroll
    for (int s = 0; s < 2; s++) {
        uint32_t ab = sa + OFF_A;
        uint32_t bb = bbase[s];
#pragma unroll
        for (int k0 = 0; k0 < 128; k0 += 16) {
            uint32_t a[4];
            ldsm4(a[0], a[1], a[2], a[3], ab + toff128(rowA, k0 + kA));
#pragma unroll
            for (int nn = 0; nn < 8; nn++) {
                uint32_t b0, b1, b2, b3;
                ldsm4(b0, b1, b2, b3, bb + toff128(nn * 16 + rowB, k0 + kB));
                mma_f16(acc[2 * nn], a, b0, b1);
                mma_f16(acc[2 * nn + 1], a, b2, b3);
            }
        }
    }

    int quad = lane >> 2;
    int cp = (lane & 3) * 2;
    int lr0 = rowBase + m0 + quad;
    int lr1 = lr0 + 8;
    bool v0 = lr0 < ndst, v1 = lr1 < ndst;
    float* sstat = (float*)(smem + OFF_STAT);

#pragma unroll
    for (int t = 0; t < 16; t++) {
        int c = t * 8 + cp;
        float x0 = acc[t][0], x1 = acc[t][1];
        float y0 = acc[t][2], y1 = acc[t][3];
        if (v0) *(float2*)(out + (size_t)(goutBase + lr0) * D + c) = make_float2(x0, x1);
        if (v1) *(float2*)(out + (size_t)(goutBase + lr1) * D + c) = make_float2(y0, y1);
        float s0 = (v0 ? x0 : 0.f) + (v1 ? y0 : 0.f);
        float s1 = (v0 ? x1 : 0.f) + (v1 ? y1 : 0.f);
        float q0 = (v0 ? x0 * x0 : 0.f) + (v1 ? y0 * y0 : 0.f);
        float q1 = (v0 ? x1 * x1 : 0.f) + (v1 ? y1 * y1 : 0.f);
#pragma unroll
        for (int S = 4; S <= 16; S <<= 1) {
            s0 += __shfl_xor_sync(0xffffffffu, s0, S);
            s1 += __shfl_xor_sync(0xffffffffu, s1, S);
            q0 += __shfl_xor_sync(0xffffffffu, q0, S);
            q1 += __shfl_xor_sync(0xffffffffu, q1, S);
        }
        if (lane < 4) {
            atomicAdd(&sstat[c], s0);
            atomicAdd(&sstat[c + 1], s1);
            atomicAdd(&sstat[128 + c], q0);
            atomicAdd(&sstat[128 + c + 1], q1);
        }
    }
    __syncthreads();
    atomicAdd(&stats[rel * 256 + tid], sstat[tid]);
}

// ---------------- BN finalize (re-zeroes stats for next layer) ----------------
__global__ void k_finalize9(const float* __restrict__ gammaL, const float* __restrict__ betaL) {
    int r = blockIdx.x;
    int c = threadIdx.x;
    float n = (float)d_ndst[r];
    float mu = g_stats[r * 256 + c] / n;
    float var = g_stats[r * 256 + 128 + c] / n - mu * mu;
    float inv = rsqrtf(var + BN_EPS);
    float sc = inv * gammaL[r * D + c];
    g_scale[r * D + c] = sc;
    g_shift[r * D + c] = betaL[r * D + c] - mu * sc;
    g_stats[r * 256 + c] = 0.f;
    g_stats[r * 256 + 128 + c] = 0.f;
}

// ------- fused normalize + 3-rel sum; layer0 -> fp16 feat, layer1 -> fp32 out ---
__global__ void k_fuse_all(const float* __restrict__ gout, Resid4 R, int layer,
                           float4* __restrict__ outF, __half* __restrict__ outH) {
    const int doff[10] = DOFF_INIT;
    int i = blockIdx.x * blockDim.x + threadIdx.x;
    if (i >= NTOT * 32) return;
    int row = i >> 5;
    int c4 = i & 31;
    int c = c4 * 4;
    int type = (row < NA) ? 0 : (row < NA + NB) ? 1 : 2;
    const int toff_[3] = {0, NA, NA + NB};
    const int rl_[3][3] = {{1, 3, 6}, {0, 5, 7}, {2, 4, 8}};
    int local = row - toff_[type];
    int r0 = rl_[type][0], r1 = rl_[type][1], r2 = rl_[type][2];
    float4 a = ((const float4*)(gout + (size_t)(doff[r0] + local) * D))[c4];
    float4 b = ((const float4*)(gout + (size_t)(doff[r1] + local) * D))[c4];
    float4 g = ((const float4*)(gout + (size_t)(doff[r2] + local) * D))[c4];
    float4 o;
    o.x = a.x * g_scale[r0 * D + c + 0] + b.x * g_scale[r1 * D + c + 0] + g.x * g_scale[r2 * D + c + 0]
        + g_shift[r0 * D + c + 0] + g_shift[r1 * D + c + 0] + g_shift[r2 * D + c + 0];
    o.y = a.y * g_scale[r0 * D + c + 1] + b.y * g_scale[r1 * D + c + 1] + g.y * g_scale[r2 * D + c + 1]
        + g_shift[r0 * D + c + 1] + g_shift[r1 * D + c + 1] + g_shift[r2 * D + c + 1];
    o.z = a.z * g_scale[r0 * D + c + 2] + b.z * g_scale[r1 * D + c + 2] + g.z * g_scale[r2 * D + c + 2]
        + g_shift[r0 * D + c + 2] + g_shift[r1 * D + c + 2] + g_shift[r2 * D + c + 2];
    o.w = a.w * g_scale[r0 * D + c + 3] + b.w * g_scale[r1 * D + c + 3] + g.w * g_scale[r2 * D + c + 3]
        + g_shift[r0 * D + c + 3] + g_shift[r1 * D + c + 3] + g_shift[r2 * D + c + 3];
    if (layer == 1) {
        float4 rr = R.f[type][(size_t)local * 32 + c4];
        o.x += rr.x; o.y += rr.y; o.z += rr.z; o.w += rr.w;
        outF[i] = o;
    } else {
        __half2 h0 = __floats2half2_rn(o.x, o.y);
        __half2 h1 = __floats2half2_rn(o.z, o.w);
        ((__half2*)outH)[i * 2] = h0;
        ((__half2*)outH)[i * 2 + 1] = h1;
    }
}

// ---------------- cleanup: restore zero-state for next call ----------------
__global__ void k_cleanup() {
    int i = blockIdx.x * blockDim.x + threadIdx.x;
    int n4 = DEG_TOT / 4;
    if (i < n4) {
        ((int4*)g_odeg)[i] = make_int4(0, 0, 0, 0);
        ((int4*)g_ideg)[i] = make_int4(0, 0, 0, 0);
    }
}

// ---------------- host orchestration ----------------
static inline int cdiv(int a, int b) { return (a + b - 1) / b; }

extern "C" void kernel_launch(void* const* d_in, const int* in_sizes, int n_in,
                              void* d_out, int out_size) {
    const float* fa = (const float*)d_in[0];
    const float* fb = (const float*)d_in[1];
    const float* fg = (const float*)d_in[2];
    const float* W = (const float*)d_in[3];
    const float* gamma = (const float*)d_in[5];
    const float* beta = (const float*)d_in[6];

    EdgePtrs E;
    for (int r = 0; r < 9; r++) {
        E.s[r] = (const int*)d_in[7 + 2 * r];
        E.d[r] = (const int*)d_in[8 + 2 * r];
    }

    float *p_gout, *p_stats;
    __half *p_wh, *p_wl, *p_mh, *p_fh;
    cudaGetSymbolAddress((void**)&p_gout, g_gout);
    cudaGetSymbolAddress((void**)&p_stats, g_stats);
    cudaGetSymbolAddress((void**)&p_wh, g_wh);
    cudaGetSymbolAddress((void**)&p_wl, g_wl);
    cudaGetSymbolAddress((void**)&p_mh, g_mh);
    cudaGetSymbolAddress((void**)&p_fh, g_fh);

    cudaFuncSetAttribute(k_gemm_all, cudaFuncAttributeMaxDynamicSharedMemorySize, SMEM_DYN);

    const int TB = 256;

    In3 IN; IN.f[0] = (const float4*)fa; IN.f[1] = (const float4*)fb; IN.f[2] = (const float4*)fg;
    Resid4 R; R.f[0] = (const float4*)fa; R.f[1] = (const float4*)fb; R.f[2] = (const float4*)fg;

    // 0: W split + degree count + feat->fp16
    k_prep<<<18 + EBLK + CBLK, TB>>>(E, W, IN);
    // 1: scan + ns/nd
    k_scan1<<<SCAN_NB, 1024>>>();
    // 2: CSR fill
    k_fill_all<<<cdiv(NE_TOT, TB), TB>>>(E);
    // 3: gather L0 (ncu target)
    k_gather_all<<<cdiv(DEG_TOT, TB / 32), TB>>>(p_fh);
    // 4: GEMM L0
    k_gemm_all<<<NTILES, 256, SMEM_DYN>>>(p_mh, p_wh, p_wl, 0, p_gout, p_stats);
    // 5: finalize L0
    k_finalize9<<<9, 128>>>(gamma, beta);
    // 6: fuse L0 -> fp16 feat
    k_fuse_all<<<cdiv(NTOT * 32, TB), TB>>>(p_gout, R, 0, nullptr, p_fh);
    // 7-10: layer 1
    k_gather_all<<<cdiv(DEG_TOT, TB / 32), TB>>>(p_fh);
    k_gemm_all<<<NTILES, 256, SMEM_DYN>>>(p_mh, p_wh, p_wl, 1, p_gout, p_stats);
    k_finalize9<<<9, 128>>>(gamma + 9 * D, beta + 9 * D);
    k_fuse_all<<<cdiv(NTOT * 32, TB), TB>>>(p_gout, R, 1, (float4*)d_out, nullptr);
    // 11: cleanup
    k_cleanup<<<cdiv(DEG_TOT / 4, TB), TB>>>();
}

// round 10
// speedup vs baseline: 1.5680x; 1.0915x over previous
#include <cuda_runtime.h>
#include <cuda_fp16.h>
#include <cstdint>

#define D 128
#define NA 100000
#define NB 150000
#define NG 2000
#define NTOT (NA + NB + NG)      // 252000
#define DEG_TOT 756000
#define NE_TOT 1352000
#define NTILES 5910
#define BN_EPS 1e-5f
#define SCAN_NB ((DEG_TOT + 1023) / 1024)   // 739

#define DOFF_INIT {0,150000,250000,252000,352000,354000,504000,604000,754000,756000}
#define SOFF_INIT {0,100000,250000,350000,352000,502000,504000,604000,754000,756000}
#define EOFF_INIT {0,300000,600000,700000,800000,950000,1100000,1200000,1350000,1352000}
#define TBASE_INIT {0,1172,1954,1970,2752,2768,3940,4722,5894,5910}
#define ST_INIT {0,1,0,2,1,2,0,1,2}

#define EBLK ((NE_TOT + 255) / 256)          // 5282
#define CBLK ((NTOT * 32 + 255) / 256)       // 31500

// ---------------- device scratch (zero-init at load; cleanup re-zeroes deg) ----
__device__ int g_odeg[DEG_TOT];                   // zero at entry (init / cleanup)
__device__ int g_ideg[DEG_TOT];                   // zero at entry
__device__ int g_offs[DEG_TOT];
__device__ int g_offs2[DEG_TOT];
__device__ int g_cursor[DEG_TOT];
__device__ int g_bsum[SCAN_NB];
__device__ int2 g_epack[NE_TOT];                  // {src_byte_off, ns fp32 bits}
__device__ float g_ns[DEG_TOT];
__device__ float g_nd[DEG_TOT];
__device__ __align__(128) __half g_fh[(size_t)NTOT * D];        // fp16 features
__device__ __align__(128) __half g_mh[(size_t)NTILES * 16384];  // A tiles fp16
__device__ float g_gout[(size_t)DEG_TOT * D];
__device__ float g_stats[9 * 2 * D];
__device__ float g_scale[9 * D];
__device__ float g_shift[9 * D];
__device__ __align__(128) __half g_wh[18 * D * D];   // W fp16, swizzled B layout

__device__ const int d_ndst[9] = {NB, NA, NG, NA, NG, NB, NA, NB, NG};

struct EdgePtrs { const int* s[9]; const int* d[9]; };
struct Resid4 { const float4* f[3]; };
struct In3 { const float4* f[3]; };

// ---------------- helpers ----------------
__device__ __forceinline__ uint32_t sw128(uint32_t o) { return o ^ ((o >> 3) & 0x70); }
__device__ __forceinline__ uint32_t toff128(uint32_t row, uint32_t k) {
    return ((k >> 6) << 14) + sw128(row * 128 + ((k & 63) << 1));
}
__device__ __forceinline__ uint32_t smem_u32(const void* p) {
    uint32_t a;
    asm("{ .reg .u64 t; cvta.to.shared.u64 t, %1; cvt.u32.u64 %0, t; }" : "=r"(a) : "l"(p));
    return a;
}
__device__ __forceinline__ void ldsm4(uint32_t& r0, uint32_t& r1, uint32_t& r2, uint32_t& r3,
                                      uint32_t addr) {
    asm volatile("ldmatrix.sync.aligned.m8n8.x4.shared.b16 {%0,%1,%2,%3}, [%4];"
                 : "=r"(r0), "=r"(r1), "=r"(r2), "=r"(r3) : "r"(addr));
}
__device__ __forceinline__ void mma_f16(float* d, const uint32_t* a, uint32_t b0, uint32_t b1) {
    asm volatile(
        "mma.sync.aligned.m16n8k16.row.col.f32.f16.f16.f32 "
        "{%0,%1,%2,%3}, {%4,%5,%6,%7}, {%8,%9}, {%0,%1,%2,%3};"
        : "+f"(d[0]), "+f"(d[1]), "+f"(d[2]), "+f"(d[3])
        : "r"(a[0]), "r"(a[1]), "r"(a[2]), "r"(a[3]), "r"(b0), "r"(b1));
}
__device__ __forceinline__ void cpasync16(uint32_t dst, const void* src) {
    asm volatile("cp.async.ca.shared.global [%0], [%1], 16;" :: "r"(dst), "l"(src));
}

// ---------------- launch 0: W->fp16 swizzled + degree count + feat->fp16 -------
__global__ void k_prep(EdgePtrs E, const float* __restrict__ W, In3 IN) {
    if (blockIdx.x < 18) {
        int rel = blockIdx.x;
        const float* w = W + (size_t)rel * D * D;
        char* wh = (char*)g_wh + (size_t)rel * D * D * 2;
        for (int idx = threadIdx.x; idx < D * D; idx += blockDim.x) {
            int k = idx >> 7, n = idx & 127;
            *(__half*)(wh + toff128(n, k)) = __float2half_rn(w[idx]);
        }
        return;
    }
    if (blockIdx.x < 18 + EBLK) {
        const int eoff[10] = EOFF_INIT;
        const int soff[10] = SOFF_INIT;
        const int doff[10] = DOFF_INIT;
        int e = (blockIdx.x - 18) * blockDim.x + threadIdx.x;
        if (e >= NE_TOT) return;
        int rel = 0;
#pragma unroll
        for (int r = 1; r < 9; r++) if (e >= eoff[r]) rel = r;
        int le = e - eoff[rel];
        atomicAdd(&g_odeg[soff[rel] + E.s[rel][le]], 1);
        atomicAdd(&g_ideg[doff[rel] + E.d[rel][le]], 1);
        return;
    }
    int i = (blockIdx.x - 18 - EBLK) * blockDim.x + threadIdx.x;
    if (i >= NTOT * 32) return;
    int t = (i < NA * 32) ? 0 : (i < (NA + NB) * 32) ? 1 : 2;
    const int base4[3] = {0, NA * 32, (NA + NB) * 32};
    float4 v = IN.f[t][i - base4[t]];
    ((__half2*)g_fh)[i * 2] = __floats2half2_rn(v.x, v.y);
    ((__half2*)g_fh)[i * 2 + 1] = __floats2half2_rn(v.z, v.w);
}

// ---------------- launch 1: scan + ns/nd + cursor/stats zero ----------------
__global__ void k_scan1() {
    int tid = threadIdx.x;
    int gid = blockIdx.x * 1024 + tid;
    int lane = tid & 31;
    int w = tid >> 5;
    int v = (gid < DEG_TOT) ? g_ideg[gid] : 0;
    if (gid < DEG_TOT) {
        int od = g_odeg[gid];
        g_ns[gid] = (od > 0) ? rsqrtf((float)od) : 0.f;
        g_nd[gid] = (v > 0) ? rsqrtf((float)v) : 0.f;
        g_cursor[gid] = 0;
    }
    if (blockIdx.x == 0) {
        for (int i = tid; i < 9 * 256; i += 1024) g_stats[i] = 0.f;
    }
    int inc = v;
#pragma unroll
    for (int s = 1; s < 32; s <<= 1) {
        int x = __shfl_up_sync(0xffffffffu, inc, s);
        if (lane >= s) inc += x;
    }
    __shared__ int wsum[32];
    if (lane == 31) wsum[w] = inc;
    __syncthreads();
    if (w == 0) {
        int x = (lane < 32) ? wsum[lane] : 0;
        int sc = x;
#pragma unroll
        for (int s = 1; s < 32; s <<= 1) {
            int y = __shfl_up_sync(0xffffffffu, sc, s);
            if (lane >= s) sc += y;
        }
        wsum[lane] = sc - x;
    }
    __syncthreads();
    int excl = inc - v + wsum[w];
    if (gid < DEG_TOT) g_offs[gid] = excl;
    if (tid == 1023) g_bsum[blockIdx.x] = excl + v;
}

// ---------------- launch 2: CSR fill (byte-offset + fp32 ns) ----------------
__global__ __launch_bounds__(256)
void k_fill_all(EdgePtrs E) {
    const int eoff[10] = EOFF_INIT;
    const int soff[10] = SOFF_INIT;
    const int doff[10] = DOFF_INIT;
    __shared__ int sb[768];
    __shared__ int wsum[8];
    int t = threadIdx.x;
    int base = t * 3;
    int a0 = (base < SCAN_NB) ? g_bsum[base] : 0;
    int a1 = (base + 1 < SCAN_NB) ? g_bsum[base + 1] : 0;
    int a2 = (base + 2 < SCAN_NB) ? g_bsum[base + 2] : 0;
    int tsum = a0 + a1 + a2;
    int lane = t & 31;
    int inc = tsum;
#pragma unroll
    for (int s = 1; s < 32; s <<= 1) {
        int x = __shfl_up_sync(0xffffffffu, inc, s);
        if (lane >= s) inc += x;
    }
    if (lane == 31) wsum[t >> 5] = inc;
    __syncthreads();
    if (t < 8) {
        int x = wsum[t];
        int sc = x;
#pragma unroll
        for (int s = 1; s < 8; s <<= 1) {
            int y = __shfl_up_sync(0xffu, sc, s);
            if (t >= s) sc += y;
        }
        wsum[t] = sc - x;
    }
    __syncthreads();
    int excl = inc - tsum + wsum[t >> 5];
    sb[base] = excl;
    sb[base + 1] = excl + a0;
    sb[base + 2] = excl + a0 + a1;
    __syncthreads();

    int e = blockIdx.x * blockDim.x + t;
    if (e >= NE_TOT) return;
    int rel = 0;
#pragma unroll
    for (int r = 1; r < 9; r++) if (e >= eoff[r]) rel = r;
    int le = e - eoff[rel];
    int ss = E.s[rel][le];
    int dd = E.d[rel][le];
    int gslot = doff[rel] + dd;
    int ofin = g_offs[gslot] + sb[gslot >> 10];
    int pos = ofin + atomicAdd(&g_cursor[gslot], 1);
    g_epack[pos] = make_int2(ss * 256, __float_as_int(g_ns[soff[rel] + ss]));
    g_offs2[gslot] = ofin;
}

// ------ gather: fp32 accumulation, byte-offset addressing -> fp16 A tiles ------
__global__ void k_gather_all(const __half* __restrict__ fh) {
    const int doff[10] = DOFF_INIT;
    const int tbase[10] = TBASE_INIT;
    const int st[9] = ST_INIT;
    const int stoff[3] = {0, NA, NA + NB};
    int row = blockIdx.x * (blockDim.x >> 5) + (threadIdx.x >> 5);
    int lane = threadIdx.x & 31;
    if (row >= DEG_TOT) return;
    int rel = 0;
#pragma unroll
    for (int r = 1; r < 9; r++) if (row >= doff[r]) rel = r;
    int lrow = row - doff[rel];
    const char* fbase = (const char*)fh + (size_t)stoff[st[rel]] * 256 + lane * 8;

    int dg = __ldg(g_cursor + row);
    float4 acc = make_float4(0.f, 0.f, 0.f, 0.f);
    if (dg > 0) {
        int o = __ldg(g_offs2 + row);
        const int2* ep = g_epack + o;
        int e = 0;
        for (; e + 2 <= dg; e += 2) {
            int2 p0 = __ldg(ep + e);
            int2 p1 = __ldg(ep + e + 1);
            float w0 = __int_as_float(p0.y);
            float w1 = __int_as_float(p1.y);
            uint2 hv0 = __ldg((const uint2*)(fbase + (uint32_t)p0.x));
            uint2 hv1 = __ldg((const uint2*)(fbase + (uint32_t)p1.x));
            float2 a0 = __half22float2(*(__half2*)&hv0.x);
            float2 a1 = __half22float2(*(__half2*)&hv0.y);
            float2 b0 = __half22float2(*(__half2*)&hv1.x);
            float2 b1 = __half22float2(*(__half2*)&hv1.y);
            acc.x += a0.x * w0 + b0.x * w1;
            acc.y += a0.y * w0 + b0.y * w1;
            acc.z += a1.x * w0 + b1.x * w1;
            acc.w += a1.y * w0 + b1.y * w1;
        }
        if (e < dg) {
            int2 p0 = __ldg(ep + e);
            float w0 = __int_as_float(p0.y);
            uint2 hv0 = __ldg((const uint2*)(fbase + (uint32_t)p0.x));
            float2 a0 = __half22float2(*(__half2*)&hv0.x);
            float2 a1 = __half22float2(*(__half2*)&hv0.y);
            acc.x += a0.x * w0;
            acc.y += a0.y * w0;
            acc.z += a1.x * w0;
            acc.w += a1.y * w0;
        }
        float ndv = __ldg(g_nd + row);
        acc.x *= ndv; acc.y *= ndv; acc.z *= ndv; acc.w *= ndv;
    }

    __half2 h0 = __floats2half2_rn(acc.x, acc.y);
    __half2 h1 = __floats2half2_rn(acc.z, acc.w);
    size_t tile = (size_t)tbase[rel] + (lrow >> 7);
    int ir = lrow & 127;
    char* bh = (char*)g_mh + tile * 32768;
    *(__half2*)(bh + toff128(ir, lane * 4)) = h0;
    *(__half2*)(bh + toff128(ir, lane * 4 + 2)) = h1;
}

// ---------------- batched GEMM (single fp16 product) + stats ----------------
#define OFF_A    0
#define OFF_B    32768
#define OFF_STAT 65536
#define SMEM_DYN (65536 + 1024 + 1024)

__global__ __launch_bounds__(256, 2)
void k_gemm_all(const __half* __restrict__ mh, const __half* __restrict__ whAll,
                int layer, float* __restrict__ out, float* __restrict__ stats) {
    const int tbase[10] = TBASE_INIT;
    const int doff[10] = DOFF_INIT;
    extern __shared__ char smem_raw[];
    char* smem = (char*)((((uintptr_t)smem_raw) + 1023) & ~(uintptr_t)1023);
    uint32_t sa = smem_u32(smem);
    int tid = threadIdx.x;
    int lane = tid & 31;
    int wid = tid >> 5;
    int bid = blockIdx.x;

    int rel = 0;
#pragma unroll
    for (int r = 1; r < 9; r++) if (bid >= tbase[r]) rel = r;
    int rowBase = (bid - tbase[rel]) * 128;
    int ndst = doff[rel + 1] - doff[rel];
    int goutBase = doff[rel];

    ((float*)(smem + OFF_STAT))[tid] = 0.f;
    {
        const char* sA = (const char*)mh + (size_t)bid * 32768;
        const char* sB = (const char*)whAll + (size_t)(layer * 9 + rel) * 32768;
#pragma unroll
        for (int i = tid; i < 2048; i += 256) {
            cpasync16(sa + OFF_A + i * 16, sA + i * 16);
            cpasync16(sa + OFF_B + i * 16, sB + i * 16);
        }
        asm volatile("cp.async.commit_group;" ::: "memory");
        asm volatile("cp.async.wait_group 0;" ::: "memory");
    }
    __syncthreads();

    float acc[16][4];
#pragma unroll
    for (int t = 0; t < 16; t++)
#pragma unroll
        for (int j = 0; j < 4; j++) acc[t][j] = 0.f;

    int m0 = wid * 16;
    uint32_t rowA = m0 + (lane & 15);
    uint32_t kA = (lane >> 4) << 3;
    uint32_t rowB = (lane & 7) + ((lane >> 4) << 3);
    uint32_t kB = ((lane >> 3) & 1) << 3;

    uint32_t ab = sa + OFF_A;
    uint32_t bb = sa + OFF_B;
#pragma unroll
    for (int k0 = 0; k0 < 128; k0 += 16) {
        uint32_t a[4];
        ldsm4(a[0], a[1], a[2], a[3], ab + toff128(rowA, k0 + kA));
#pragma unroll
        for (int nn = 0; nn < 8; nn++) {
            uint32_t b0, b1, b2, b3;
            ldsm4(b0, b1, b2, b3, bb + toff128(nn * 16 + rowB, k0 + kB));
            mma_f16(acc[2 * nn], a, b0, b1);
            mma_f16(acc[2 * nn + 1], a, b2, b3);
        }
    }

    int quad = lane >> 2;
    int cp = (lane & 3) * 2;
    int lr0 = rowBase + m0 + quad;
    int lr1 = lr0 + 8;
    bool v0 = lr0 < ndst, v1 = lr1 < ndst;
    float* sstat = (float*)(smem + OFF_STAT);

#pragma unroll
    for (int t = 0; t < 16; t++) {
        int c = t * 8 + cp;
        float x0 = acc[t][0], x1 = acc[t][1];
        float y0 = acc[t][2], y1 = acc[t][3];
        if (v0) *(float2*)(out + (size_t)(goutBase + lr0) * D + c) = make_float2(x0, x1);
        if (v1) *(float2*)(out + (size_t)(goutBase + lr1) * D + c) = make_float2(y0, y1);
        float s0 = (v0 ? x0 : 0.f) + (v1 ? y0 : 0.f);
        float s1 = (v0 ? x1 : 0.f) + (v1 ? y1 : 0.f);
        float q0 = (v0 ? x0 * x0 : 0.f) + (v1 ? y0 * y0 : 0.f);
        float q1 = (v0 ? x1 * x1 : 0.f) + (v1 ? y1 * y1 : 0.f);
#pragma unroll
        for (int S = 4; S <= 16; S <<= 1) {
            s0 += __shfl_xor_sync(0xffffffffu, s0, S);
            s1 += __shfl_xor_sync(0xffffffffu, s1, S);
            q0 += __shfl_xor_sync(0xffffffffu, q0, S);
            q1 += __shfl_xor_sync(0xffffffffu, q1, S);
        }
        if (lane < 4) {
            atomicAdd(&sstat[c], s0);
            atomicAdd(&sstat[c + 1], s1);
            atomicAdd(&sstat[128 + c], q0);
            atomicAdd(&sstat[128 + c + 1], q1);
        }
    }
    __syncthreads();
    atomicAdd(&stats[rel * 256 + tid], sstat[tid]);
}

// ---------------- BN finalize ----------------
__global__ void k_finalize9(const float* __restrict__ gammaL, const float* __restrict__ betaL) {
    int r = blockIdx.x;
    int c = threadIdx.x;
    float n = (float)d_ndst[r];
    float mu = g_stats[r * 256 + c] / n;
    float var = g_stats[r * 256 + 128 + c] / n - mu * mu;
    float inv = rsqrtf(var + BN_EPS);
    float sc = inv * gammaL[r * D + c];
    g_scale[r * D + c] = sc;
    g_shift[r * D + c] = betaL[r * D + c] - mu * sc;
    g_stats[r * 256 + c] = 0.f;
    g_stats[r * 256 + 128 + c] = 0.f;
}

// ------- fused normalize + 3-rel sum; layer0 -> fp16 feat, layer1 -> fp32 out ---
__global__ void k_fuse_all(const float* __restrict__ gout, Resid4 R, int layer,
                           float4* __restrict__ outF, __half* __restrict__ outH) {
    const int doff[10] = DOFF_INIT;
    int i = blockIdx.x * blockDim.x + threadIdx.x;
    if (i >= NTOT * 32) return;
    int row = i >> 5;
    int c4 = i & 31;
    int c = c4 * 4;
    int type = (row < NA) ? 0 : (row < NA + NB) ? 1 : 2;
    const int toff_[3] = {0, NA, NA + NB};
    const int rl_[3][3] = {{1, 3, 6}, {0, 5, 7}, {2, 4, 8}};
    int local = row - toff_[type];
    int r0 = rl_[type][0], r1 = rl_[type][1], r2 = rl_[type][2];
    float4 a = ((const float4*)(gout + (size_t)(doff[r0] + local) * D))[c4];
    float4 b = ((const float4*)(gout + (size_t)(doff[r1] + local) * D))[c4];
    float4 g = ((const float4*)(gout + (size_t)(doff[r2] + local) * D))[c4];
    float4 o;
    o.x = a.x * g_scale[r0 * D + c + 0] + b.x * g_scale[r1 * D + c + 0] + g.x * g_scale[r2 * D + c + 0]
        + g_shift[r0 * D + c + 0] + g_shift[r1 * D + c + 0] + g_shift[r2 * D + c + 0];
    o.y = a.y * g_scale[r0 * D + c + 1] + b.y * g_scale[r1 * D + c + 1] + g.y * g_scale[r2 * D + c + 1]
        + g_shift[r0 * D + c + 1] + g_shift[r1 * D + c + 1] + g_shift[r2 * D + c + 1];
    o.z = a.z * g_scale[r0 * D + c + 2] + b.z * g_scale[r1 * D + c + 2] + g.z * g_scale[r2 * D + c + 2]
        + g_shift[r0 * D + c + 2] + g_shift[r1 * D + c + 2] + g_shift[r2 * D + c + 2];
    o.w = a.w * g_scale[r0 * D + c + 3] + b.w * g_scale[r1 * D + c + 3] + g.w * g_scale[r2 * D + c + 3]
        + g_shift[r0 * D + c + 3] + g_shift[r1 * D + c + 3] + g_shift[r2 * D + c + 3];
    if (layer == 1) {
        float4 rr = R.f[type][(size_t)local * 32 + c4];
        o.x += rr.x; o.y += rr.y; o.z += rr.z; o.w += rr.w;
        outF[i] = o;
    } else {
        ((__half2*)outH)[i * 2] = __floats2half2_rn(o.x, o.y);
        ((__half2*)outH)[i * 2 + 1] = __floats2half2_rn(o.z, o.w);
    }
}

// ---------------- cleanup ----------------
__global__ void k_cleanup() {
    int i = blockIdx.x * blockDim.x + threadIdx.x;
    int n4 = DEG_TOT / 4;
    if (i < n4) {
        ((int4*)g_odeg)[i] = make_int4(0, 0, 0, 0);
        ((int4*)g_ideg)[i] = make_int4(0, 0, 0, 0);
    }
}

// ---------------- host orchestration ----------------
static inline int cdiv(int a, int b) { return (a + b - 1) / b; }

extern "C" void kernel_launch(void* const* d_in, const int* in_sizes, int n_in,
                              void* d_out, int out_size) {
    const float* fa = (const float*)d_in[0];
    const float* fb = (const float*)d_in[1];
    const float* fg = (const float*)d_in[2];
    const float* W = (const float*)d_in[3];
    const float* gamma = (const float*)d_in[5];
    const float* beta = (const float*)d_in[6];

    EdgePtrs E;
    for (int r = 0; r < 9; r++) {
        E.s[r] = (const int*)d_in[7 + 2 * r];
        E.d[r] = (const int*)d_in[8 + 2 * r];
    }

    float *p_gout, *p_stats;
    __half *p_wh, *p_mh, *p_fh;
    cudaGetSymbolAddress((void**)&p_gout, g_gout);
    cudaGetSymbolAddress((void**)&p_stats, g_stats);
    cudaGetSymbolAddress((void**)&p_wh, g_wh);
    cudaGetSymbolAddress((void**)&p_mh, g_mh);
    cudaGetSymbolAddress((void**)&p_fh, g_fh);

    cudaFuncSetAttribute(k_gemm_all, cudaFuncAttributeMaxDynamicSharedMemorySize, SMEM_DYN);

    const int TB = 256;

    In3 IN; IN.f[0] = (const float4*)fa; IN.f[1] = (const float4*)fb; IN.f[2] = (const float4*)fg;
    Resid4 R; R.f[0] = (const float4*)fa; R.f[1] = (const float4*)fb; R.f[2] = (const float4*)fg;

    // 0: W->fp16 + degree count + feat->fp16
    k_prep<<<18 + EBLK + CBLK, TB>>>(E, W, IN);
    // 1: scan + ns/nd
    k_scan1<<<SCAN_NB, 1024>>>();
    // 2: CSR fill
    k_fill_all<<<cdiv(NE_TOT, TB), TB>>>(E);
    // 3: gather L0 (ncu target)
    k_gather_all<<<cdiv(DEG_TOT, TB / 32), TB>>>(p_fh);
    // 4: GEMM L0
    k_gemm_all<<<NTILES, 256, SMEM_DYN>>>(p_mh, p_wh, 0, p_gout, p_stats);
    // 5: finalize L0
    k_finalize9<<<9, 128>>>(gamma, beta);
    // 6: fuse L0 -> fp16 feat
    k_fuse_all<<<cdiv(NTOT * 32, TB), TB>>>(p_gout, R, 0, nullptr, p_fh);
    // 7-10: layer 1
    k_gather_all<<<cdiv(DEG_TOT, TB / 32), TB>>>(p_fh);
    k_gemm_all<<<NTILES, 256, SMEM_DYN>>>(p_mh, p_wh, 1, p_gout, p_stats);
    k_finalize9<<<9, 128>>>(gamma + 9 * D, beta + 9 * D);
    k_fuse_all<<<cdiv(NTOT * 32, TB), TB>>>(p_gout, R, 1, (float4*)d_out, nullptr);
    // 11: cleanup
    k_cleanup<<<cdiv(DEG_TOT / 4, TB), TB>>>();
}

// round 11
// speedup vs baseline: 1.9953x; 1.2725x over previous
#include <cuda_runtime.h>
#include <cuda_fp16.h>
#include <cstdint>

#define D 128
#define NA 100000
#define NB 150000
#define NG 2000
#define NTOT (NA + NB + NG)      // 252000
#define DEG_TOT 756000
#define NE_TOT 1352000
#define NTILES 5910
#define BN_EPS 1e-5f
#define SCAN_NB ((DEG_TOT + 1023) / 1024)   // 739

#define EBLK ((NE_TOT + 255) / 256)          // 5282
#define CBLK ((NTOT * 32 + 255) / 256)       // 31500

// ---------------- constant boundary tables (LDC, no local-mem materialization) --
__constant__ int c_doff[10] = {0,150000,250000,252000,352000,354000,504000,604000,754000,756000};
__constant__ int c_soff[10] = {0,100000,250000,350000,352000,502000,504000,604000,754000,756000};
__constant__ int c_eoff[10] = {0,300000,600000,700000,800000,950000,1100000,1200000,1350000,1352000};
__constant__ int c_tbase[10] = {0,1172,1954,1970,2752,2768,3940,4722,5894,5910};
__constant__ int c_stoff[9] = {0, NA, 0, NA + NB, NA, NA + NB, 0, NA, NA + NB}; // stoff[st[rel]]
__constant__ int c_ndst[9] = {NB, NA, NG, NA, NG, NB, NA, NB, NG};
__constant__ int c_rl[9] = {1, 3, 6, 0, 5, 7, 2, 4, 8};   // rels feeding type t at [3t..3t+2]
__constant__ int c_toff[3] = {0, NA, NA + NB};

// ---------------- device scratch (zero-init at load; cleanup re-zeroes deg) ----
__device__ int g_odeg[DEG_TOT];
__device__ int g_ideg[DEG_TOT];
__device__ int g_offs[DEG_TOT];
__device__ int g_offs2[DEG_TOT];
__device__ int g_cursor[DEG_TOT];
__device__ int g_bsum[SCAN_NB];
__device__ int2 g_epack[NE_TOT];                  // {src_byte_off, ns fp32 bits}
__device__ float g_ns[DEG_TOT];
__device__ float g_nd[DEG_TOT];
__device__ __align__(128) __half g_fh[(size_t)NTOT * D];        // fp16 features
__device__ __align__(128) __half g_mh[(size_t)NTILES * 16384];  // A tiles fp16
__device__ __align__(128) __half g_gout[(size_t)DEG_TOT * D];   // fp16 gout
__device__ float g_stats[9 * 2 * D];
__device__ float g_scale[9 * D];
__device__ float g_shift[9 * D];
__device__ __align__(128) __half g_wh[18 * D * D];   // W fp16, swizzled B layout

struct EdgePtrs { const int* s[9]; const int* d[9]; };

// ---------------- helpers ----------------
__device__ __forceinline__ uint32_t sw128(uint32_t o) { return o ^ ((o >> 3) & 0x70); }
__device__ __forceinline__ uint32_t toff128(uint32_t row, uint32_t k) {
    return ((k >> 6) << 14) + sw128(row * 128 + ((k & 63) << 1));
}
__device__ __forceinline__ uint32_t smem_u32(const void* p) {
    uint32_t a;
    asm("{ .reg .u64 t; cvta.to.shared.u64 t, %1; cvt.u32.u64 %0, t; }" : "=r"(a) : "l"(p));
    return a;
}
__device__ __forceinline__ void ldsm4(uint32_t& r0, uint32_t& r1, uint32_t& r2, uint32_t& r3,
                                      uint32_t addr) {
    asm volatile("ldmatrix.sync.aligned.m8n8.x4.shared.b16 {%0,%1,%2,%3}, [%4];"
                 : "=r"(r0), "=r"(r1), "=r"(r2), "=r"(r3) : "r"(addr));
}
__device__ __forceinline__ void mma_f16(float* d, const uint32_t* a, uint32_t b0, uint32_t b1) {
    asm volatile(
        "mma.sync.aligned.m16n8k16.row.col.f32.f16.f16.f32 "
        "{%0,%1,%2,%3}, {%4,%5,%6,%7}, {%8,%9}, {%0,%1,%2,%3};"
        : "+f"(d[0]), "+f"(d[1]), "+f"(d[2]), "+f"(d[3])
        : "r"(a[0]), "r"(a[1]), "r"(a[2]), "r"(a[3]), "r"(b0), "r"(b1));
}
__device__ __forceinline__ void cpasync16(uint32_t dst, const void* src) {
    asm volatile("cp.async.ca.shared.global [%0], [%1], 16;" :: "r"(dst), "l"(src));
}

// ---------------- launch 0: W->fp16 swizzled + degree count + feat->fp16 -------
__global__ void k_prep(EdgePtrs E, const float* __restrict__ W,
                       const float4* __restrict__ fa4, const float4* __restrict__ fb4,
                       const float4* __restrict__ fg4) {
    if (blockIdx.x < 18) {
        int rel = blockIdx.x;
        const float* w = W + (size_t)rel * D * D;
        char* wh = (char*)g_wh + (size_t)rel * D * D * 2;
        for (int idx = threadIdx.x; idx < D * D; idx += blockDim.x) {
            int k = idx >> 7, n = idx & 127;
            *(__half*)(wh + toff128(n, k)) = __float2half_rn(w[idx]);
        }
        return;
    }
    if (blockIdx.x < 18 + EBLK) {
        int e = (blockIdx.x - 18) * blockDim.x + threadIdx.x;
        if (e >= NE_TOT) return;
        int rel = 0;
#pragma unroll
        for (int r = 1; r < 9; r++) if (e >= c_eoff[r]) rel = r;
        int le = e - c_eoff[rel];
        atomicAdd(&g_odeg[c_soff[rel] + E.s[rel][le]], 1);
        atomicAdd(&g_ideg[c_doff[rel] + E.d[rel][le]], 1);
        return;
    }
    int i = (blockIdx.x - 18 - EBLK) * blockDim.x + threadIdx.x;
    if (i >= NTOT * 32) return;
    int t = (i < NA * 32) ? 0 : (i < (NA + NB) * 32) ? 1 : 2;
    const float4* src = (t == 0) ? fa4 : (t == 1) ? fb4 : fg4;
    int base4 = (t == 0) ? 0 : (t == 1) ? NA * 32 : (NA + NB) * 32;
    float4 v = src[i - base4];
    ((__half2*)g_fh)[i * 2] = __floats2half2_rn(v.x, v.y);
    ((__half2*)g_fh)[i * 2 + 1] = __floats2half2_rn(v.z, v.w);
}

// ---------------- launch 1: scan + ns/nd + cursor/stats zero ----------------
__global__ void k_scan1() {
    int tid = threadIdx.x;
    int gid = blockIdx.x * 1024 + tid;
    int lane = tid & 31;
    int w = tid >> 5;
    int v = (gid < DEG_TOT) ? g_ideg[gid] : 0;
    if (gid < DEG_TOT) {
        int od = g_odeg[gid];
        g_ns[gid] = (od > 0) ? rsqrtf((float)od) : 0.f;
        g_nd[gid] = (v > 0) ? rsqrtf((float)v) : 0.f;
        g_cursor[gid] = 0;
    }
    if (blockIdx.x == 0) {
        for (int i = tid; i < 9 * 256; i += 1024) g_stats[i] = 0.f;
    }
    int inc = v;
#pragma unroll
    for (int s = 1; s < 32; s <<= 1) {
        int x = __shfl_up_sync(0xffffffffu, inc, s);
        if (lane >= s) inc += x;
    }
    __shared__ int wsum[32];
    if (lane == 31) wsum[w] = inc;
    __syncthreads();
    if (w == 0) {
        int x = (lane < 32) ? wsum[lane] : 0;
        int sc = x;
#pragma unroll
        for (int s = 1; s < 32; s <<= 1) {
            int y = __shfl_up_sync(0xffffffffu, sc, s);
            if (lane >= s) sc += y;
        }
        wsum[lane] = sc - x;
    }
    __syncthreads();
    int excl = inc - v + wsum[w];
    if (gid < DEG_TOT) g_offs[gid] = excl;
    if (tid == 1023) g_bsum[blockIdx.x] = excl + v;
}

// ---------------- launch 2: CSR fill ----------------
__global__ __launch_bounds__(256)
void k_fill_all(EdgePtrs E) {
    __shared__ int sb[768];
    __shared__ int wsum[8];
    int t = threadIdx.x;
    int base = t * 3;
    int a0 = (base < SCAN_NB) ? g_bsum[base] : 0;
    int a1 = (base + 1 < SCAN_NB) ? g_bsum[base + 1] : 0;
    int a2 = (base + 2 < SCAN_NB) ? g_bsum[base + 2] : 0;
    int tsum = a0 + a1 + a2;
    int lane = t & 31;
    int inc = tsum;
#pragma unroll
    for (int s = 1; s < 32; s <<= 1) {
        int x = __shfl_up_sync(0xffffffffu, inc, s);
        if (lane >= s) inc += x;
    }
    if (lane == 31) wsum[t >> 5] = inc;
    __syncthreads();
    if (t < 8) {
        int x = wsum[t];
        int sc = x;
#pragma unroll
        for (int s = 1; s < 8; s <<= 1) {
            int y = __shfl_up_sync(0xffu, sc, s);
            if (t >= s) sc += y;
        }
        wsum[t] = sc - x;
    }
    __syncthreads();
    int excl = inc - tsum + wsum[t >> 5];
    sb[base] = excl;
    sb[base + 1] = excl + a0;
    sb[base + 2] = excl + a0 + a1;
    __syncthreads();

    int e = blockIdx.x * blockDim.x + t;
    if (e >= NE_TOT) return;
    int rel = 0;
#pragma unroll
    for (int r = 1; r < 9; r++) if (e >= c_eoff[r]) rel = r;
    int le = e - c_eoff[rel];
    int ss = E.s[rel][le];
    int dd = E.d[rel][le];
    int gslot = c_doff[rel] + dd;
    int ofin = g_offs[gslot] + sb[gslot >> 10];
    int pos = ofin + atomicAdd(&g_cursor[gslot], 1);
    g_epack[pos] = make_int2(ss * 256, __float_as_int(g_ns[c_soff[rel] + ss]));
    g_offs2[gslot] = ofin;
}

// ------ gather: fp32 accumulation, byte-offset addressing -> fp16 A tiles ------
__global__ void k_gather_all(const __half* __restrict__ fh) {
    int row = blockIdx.x * (blockDim.x >> 5) + (threadIdx.x >> 5);
    int lane = threadIdx.x & 31;
    if (row >= DEG_TOT) return;
    int rel = 0;
#pragma unroll
    for (int r = 1; r < 9; r++) if (row >= c_doff[r]) rel = r;
    int lrow = row - c_doff[rel];
    const char* fbase = (const char*)fh + (size_t)c_stoff[rel] * 256 + lane * 8;

    int dg = __ldg(g_cursor + row);
    float4 acc = make_float4(0.f, 0.f, 0.f, 0.f);
    if (dg > 0) {
        int o = __ldg(g_offs2 + row);
        const int2* ep = g_epack + o;
        int e = 0;
        for (; e + 4 <= dg; e += 4) {
            int2 p0 = __ldg(ep + e);
            int2 p1 = __ldg(ep + e + 1);
            int2 p2 = __ldg(ep + e + 2);
            int2 p3 = __ldg(ep + e + 3);
            uint2 h0 = __ldg((const uint2*)(fbase + (uint32_t)p0.x));
            uint2 h1 = __ldg((const uint2*)(fbase + (uint32_t)p1.x));
            uint2 h2 = __ldg((const uint2*)(fbase + (uint32_t)p2.x));
            uint2 h3 = __ldg((const uint2*)(fbase + (uint32_t)p3.x));
            float w0 = __int_as_float(p0.y), w1 = __int_as_float(p1.y);
            float w2 = __int_as_float(p2.y), w3 = __int_as_float(p3.y);
            float2 a0 = __half22float2(*(__half2*)&h0.x), a1 = __half22float2(*(__half2*)&h0.y);
            float2 b0 = __half22float2(*(__half2*)&h1.x), b1 = __half22float2(*(__half2*)&h1.y);
            float2 d0 = __half22float2(*(__half2*)&h2.x), d1 = __half22float2(*(__half2*)&h2.y);
            float2 e0 = __half22float2(*(__half2*)&h3.x), e1 = __half22float2(*(__half2*)&h3.y);
            acc.x += a0.x * w0 + b0.x * w1 + d0.x * w2 + e0.x * w3;
            acc.y += a0.y * w0 + b0.y * w1 + d0.y * w2 + e0.y * w3;
            acc.z += a1.x * w0 + b1.x * w1 + d1.x * w2 + e1.x * w3;
            acc.w += a1.y * w0 + b1.y * w1 + d1.y * w2 + e1.y * w3;
        }
        for (; e < dg; e++) {
            int2 p0 = __ldg(ep + e);
            float w0 = __int_as_float(p0.y);
            uint2 h0 = __ldg((const uint2*)(fbase + (uint32_t)p0.x));
            float2 a0 = __half22float2(*(__half2*)&h0.x);
            float2 a1 = __half22float2(*(__half2*)&h0.y);
            acc.x += a0.x * w0;
            acc.y += a0.y * w0;
            acc.z += a1.x * w0;
            acc.w += a1.y * w0;
        }
        float ndv = __ldg(g_nd + row);
        acc.x *= ndv; acc.y *= ndv; acc.z *= ndv; acc.w *= ndv;
    }

    __half2 h0 = __floats2half2_rn(acc.x, acc.y);
    __half2 h1 = __floats2half2_rn(acc.z, acc.w);
    size_t tile = (size_t)c_tbase[rel] + (lrow >> 7);
    int ir = lrow & 127;
    char* bh = (char*)g_mh + tile * 32768;
    *(__half2*)(bh + toff128(ir, lane * 4)) = h0;
    *(__half2*)(bh + toff128(ir, lane * 4 + 2)) = h1;
}

// ---------------- batched GEMM (single fp16 product) + stats ----------------
#define OFF_A    0
#define OFF_B    32768
#define OFF_STAT 65536
#define SMEM_DYN (65536 + 1024 + 1024)

__global__ __launch_bounds__(256, 2)
void k_gemm_all(const __half* __restrict__ mh, const __half* __restrict__ whAll,
                int layer, __half* __restrict__ out, float* __restrict__ stats) {
    extern __shared__ char smem_raw[];
    char* smem = (char*)((((uintptr_t)smem_raw) + 1023) & ~(uintptr_t)1023);
    uint32_t sa = smem_u32(smem);
    int tid = threadIdx.x;
    int lane = tid & 31;
    int wid = tid >> 5;
    int bid = blockIdx.x;

    int rel = 0;
#pragma unroll
    for (int r = 1; r < 9; r++) if (bid >= c_tbase[r]) rel = r;
    int rowBase = (bid - c_tbase[rel]) * 128;
    int ndst = c_doff[rel + 1] - c_doff[rel];
    int goutBase = c_doff[rel];

    ((float*)(smem + OFF_STAT))[tid] = 0.f;
    {
        const char* sA = (const char*)mh + (size_t)bid * 32768;
        const char* sB = (const char*)whAll + (size_t)(layer * 9 + rel) * 32768;
#pragma unroll
        for (int i = tid; i < 2048; i += 256) {
            cpasync16(sa + OFF_A + i * 16, sA + i * 16);
            cpasync16(sa + OFF_B + i * 16, sB + i * 16);
        }
        asm volatile("cp.async.commit_group;" ::: "memory");
        asm volatile("cp.async.wait_group 0;" ::: "memory");
    }
    __syncthreads();

    float acc[16][4];
#pragma unroll
    for (int t = 0; t < 16; t++)
#pragma unroll
        for (int j = 0; j < 4; j++) acc[t][j] = 0.f;

    int m0 = wid * 16;
    uint32_t rowA = m0 + (lane & 15);
    uint32_t kA = (lane >> 4) << 3;
    uint32_t rowB = (lane & 7) + ((lane >> 4) << 3);
    uint32_t kB = ((lane >> 3) & 1) << 3;

    uint32_t ab = sa + OFF_A;
    uint32_t bb = sa + OFF_B;
#pragma unroll
    for (int k0 = 0; k0 < 128; k0 += 16) {
        uint32_t a[4];
        ldsm4(a[0], a[1], a[2], a[3], ab + toff128(rowA, k0 + kA));
#pragma unroll
        for (int nn = 0; nn < 8; nn++) {
            uint32_t b0, b1, b2, b3;
            ldsm4(b0, b1, b2, b3, bb + toff128(nn * 16 + rowB, k0 + kB));
            mma_f16(acc[2 * nn], a, b0, b1);
            mma_f16(acc[2 * nn + 1], a, b2, b3);
        }
    }

    int quad = lane >> 2;
    int cp = (lane & 3) * 2;
    int lr0 = rowBase + m0 + quad;
    int lr1 = lr0 + 8;
    bool v0 = lr0 < ndst, v1 = lr1 < ndst;
    float* sstat = (float*)(smem + OFF_STAT);

#pragma unroll
    for (int t = 0; t < 16; t++) {
        int c = t * 8 + cp;
        float x0 = acc[t][0], x1 = acc[t][1];
        float y0 = acc[t][2], y1 = acc[t][3];
        if (v0) *(__half2*)(out + (size_t)(goutBase + lr0) * D + c) = __floats2half2_rn(x0, x1);
        if (v1) *(__half2*)(out + (size_t)(goutBase + lr1) * D + c) = __floats2half2_rn(y0, y1);
        float s0 = (v0 ? x0 : 0.f) + (v1 ? y0 : 0.f);
        float s1 = (v0 ? x1 : 0.f) + (v1 ? y1 : 0.f);
        float q0 = (v0 ? x0 * x0 : 0.f) + (v1 ? y0 * y0 : 0.f);
        float q1 = (v0 ? x1 * x1 : 0.f) + (v1 ? y1 * y1 : 0.f);
#pragma unroll
        for (int S = 4; S <= 16; S <<= 1) {
            s0 += __shfl_xor_sync(0xffffffffu, s0, S);
            s1 += __shfl_xor_sync(0xffffffffu, s1, S);
            q0 += __shfl_xor_sync(0xffffffffu, q0, S);
            q1 += __shfl_xor_sync(0xffffffffu, q1, S);
        }
        if (lane < 4) {
            atomicAdd(&sstat[c], s0);
            atomicAdd(&sstat[c + 1], s1);
            atomicAdd(&sstat[128 + c], q0);
            atomicAdd(&sstat[128 + c + 1], q1);
        }
    }
    __syncthreads();
    atomicAdd(&stats[rel * 256 + tid], sstat[tid]);
}

// ---------------- BN finalize (re-zeroes stats for next layer) ----------------
__global__ void k_finalize9(const float* __restrict__ gammaL, const float* __restrict__ betaL) {
    int r = blockIdx.x;
    int c = threadIdx.x;
    float n = (float)c_ndst[r];
    float mu = g_stats[r * 256 + c] / n;
    float var = g_stats[r * 256 + 128 + c] / n - mu * mu;
    float inv = rsqrtf(var + BN_EPS);
    float sc = inv * gammaL[r * D + c];
    g_scale[r * D + c] = sc;
    g_shift[r * D + c] = betaL[r * D + c] - mu * sc;
    g_stats[r * 256 + c] = 0.f;
    g_stats[r * 256 + 128 + c] = 0.f;
}

// ------- fused normalize + 3-rel sum; layer0 -> fp16 feat, layer1 -> fp32 out ---
__global__ void k_fuse_all(const __half* __restrict__ gout,
                           const float4* __restrict__ ra, const float4* __restrict__ rb,
                           const float4* __restrict__ rg, int layer,
                           float4* __restrict__ outF, __half* __restrict__ outH) {
    int i = blockIdx.x * blockDim.x + threadIdx.x;
    if (i >= NTOT * 32) return;
    int row = i >> 5;
    int c4 = i & 31;
    int c = c4 * 4;
    int type = (row < NA) ? 0 : (row < NA + NB) ? 1 : 2;
    int local = row - c_toff[type];
    int r0 = c_rl[type * 3], r1 = c_rl[type * 3 + 1], r2 = c_rl[type * 3 + 2];

    uint2 ha = *(const uint2*)(gout + (size_t)(c_doff[r0] + local) * D + c);
    uint2 hb = *(const uint2*)(gout + (size_t)(c_doff[r1] + local) * D + c);
    uint2 hg = *(const uint2*)(gout + (size_t)(c_doff[r2] + local) * D + c);
    float2 a01 = __half22float2(*(__half2*)&ha.x), a23 = __half22float2(*(__half2*)&ha.y);
    float2 b01 = __half22float2(*(__half2*)&hb.x), b23 = __half22float2(*(__half2*)&hb.y);
    float2 g01 = __half22float2(*(__half2*)&hg.x), g23 = __half22float2(*(__half2*)&hg.y);

    float4 o;
    o.x = a01.x * g_scale[r0 * D + c + 0] + b01.x * g_scale[r1 * D + c + 0] + g01.x * g_scale[r2 * D + c + 0]
        + g_shift[r0 * D + c + 0] + g_shift[r1 * D + c + 0] + g_shift[r2 * D + c + 0];
    o.y = a01.y * g_scale[r0 * D + c + 1] + b01.y * g_scale[r1 * D + c + 1] + g01.y * g_scale[r2 * D + c + 1]
        + g_shift[r0 * D + c + 1] + g_shift[r1 * D + c + 1] + g_shift[r2 * D + c + 1];
    o.z = a23.x * g_scale[r0 * D + c + 2] + b23.x * g_scale[r1 * D + c + 2] + g23.x * g_scale[r2 * D + c + 2]
        + g_shift[r0 * D + c + 2] + g_shift[r1 * D + c + 2] + g_shift[r2 * D + c + 2];
    o.w = a23.y * g_scale[r0 * D + c + 3] + b23.y * g_scale[r1 * D + c + 3] + g23.y * g_scale[r2 * D + c + 3]
        + g_shift[r0 * D + c + 3] + g_shift[r1 * D + c + 3] + g_shift[r2 * D + c + 3];
    if (layer == 1) {
        const float4* rp = (type == 0) ? ra : (type == 1) ? rb : rg;
        float4 rr = rp[(size_t)local * 32 + c4];
        o.x += rr.x; o.y += rr.y; o.z += rr.z; o.w += rr.w;
        outF[i] = o;
    } else {
        ((__half2*)outH)[i * 2] = __floats2half2_rn(o.x, o.y);
        ((__half2*)outH)[i * 2 + 1] = __floats2half2_rn(o.z, o.w);
    }
}

// ---------------- cleanup ----------------
__global__ void k_cleanup() {
    int i = blockIdx.x * blockDim.x + threadIdx.x;
    int n4 = DEG_TOT / 4;
    if (i < n4) {
        ((int4*)g_odeg)[i] = make_int4(0, 0, 0, 0);
        ((int4*)g_ideg)[i] = make_int4(0, 0, 0, 0);
    }
}

// ---------------- host orchestration ----------------
static inline int cdiv(int a, int b) { return (a + b - 1) / b; }

extern "C" void kernel_launch(void* const* d_in, const int* in_sizes, int n_in,
                              void* d_out, int out_size) {
    const float* fa = (const float*)d_in[0];
    const float* fb = (const float*)d_in[1];
    const float* fg = (const float*)d_in[2];
    const float* W = (const float*)d_in[3];
    const float* gamma = (const float*)d_in[5];
    const float* beta = (const float*)d_in[6];

    EdgePtrs E;
    for (int r = 0; r < 9; r++) {
        E.s[r] = (const int*)d_in[7 + 2 * r];
        E.d[r] = (const int*)d_in[8 + 2 * r];
    }

    float* p_stats;
    __half *p_wh, *p_mh, *p_fh, *p_gout;
    cudaGetSymbolAddress((void**)&p_gout, g_gout);
    cudaGetSymbolAddress((void**)&p_stats, g_stats);
    cudaGetSymbolAddress((void**)&p_wh, g_wh);
    cudaGetSymbolAddress((void**)&p_mh, g_mh);
    cudaGetSymbolAddress((void**)&p_fh, g_fh);

    cudaFuncSetAttribute(k_gemm_all, cudaFuncAttributeMaxDynamicSharedMemorySize, SMEM_DYN);

    const int TB = 256;

    // 0: W->fp16 + degree count + feat->fp16
    k_prep<<<18 + EBLK + CBLK, TB>>>(E, W, (const float4*)fa, (const float4*)fb,
                                     (const float4*)fg);
    // 1: scan + ns/nd
    k_scan1<<<SCAN_NB, 1024>>>();
    // 2: CSR fill
    k_fill_all<<<cdiv(NE_TOT, TB), TB>>>(E);
    // 3: gather L0 (ncu target)
    k_gather_all<<<cdiv(DEG_TOT, TB / 32), TB>>>(p_fh);
    // 4: GEMM L0
    k_gemm_all<<<NTILES, 256, SMEM_DYN>>>(p_mh, p_wh, 0, p_gout, p_stats);
    // 5: finalize L0
    k_finalize9<<<9, 128>>>(gamma, beta);
    // 6: fuse L0 -> fp16 feat
    k_fuse_all<<<cdiv(NTOT * 32, TB), TB>>>(p_gout, (const float4*)fa, (const float4*)fb,
                                            (const float4*)fg, 0, nullptr, p_fh);
    // 7-10: layer 1
    k_gather_all<<<cdiv(DEG_TOT, TB / 32), TB>>>(p_fh);
    k_gemm_all<<<NTILES, 256, SMEM_DYN>>>(p_mh, p_wh, 1, p_gout, p_stats);
    k_finalize9<<<9, 128>>>(gamma + 9 * D, beta + 9 * D);
    k_fuse_all<<<cdiv(NTOT * 32, TB), TB>>>(p_gout, (const float4*)fa, (const float4*)fb,
                                            (const float4*)fg, 1, (float4*)d_out, nullptr);
    // 11: cleanup
    k_cleanup<<<cdiv(DEG_TOT / 4, TB), TB>>>();
}

// round 12
// speedup vs baseline: 2.3731x; 1.1893x over previous
#include <cuda_runtime.h>
#include <cuda_fp16.h>
#include <cstdint>

#define D 128
#define NA 100000
#define NB 150000
#define NG 2000
#define NTOT (NA + NB + NG)      // 252000
#define DEG_TOT 756000
#define NE_TOT 1352000
#define NTILES 5910
#define BN_EPS 1e-5f
#define SCAN_NB ((DEG_TOT + 1023) / 1024)   // 739

#define EBLK ((NE_TOT + 255) / 256)          // 5282
#define CBLK ((NTOT * 32 + 255) / 256)       // 31500

// ---------------- constant boundary tables ----------------
__constant__ int c_doff[10] = {0,150000,250000,252000,352000,354000,504000,604000,754000,756000};
__constant__ int c_soff[10] = {0,100000,250000,350000,352000,502000,504000,604000,754000,756000};
__constant__ int c_eoff[10] = {0,300000,600000,700000,800000,950000,1100000,1200000,1350000,1352000};
__constant__ int c_tbase[10] = {0,1172,1954,1970,2752,2768,3940,4722,5894,5910};
__constant__ int c_stoff[9] = {0, NA, 0, NA + NB, NA, NA + NB, 0, NA, NA + NB};
__constant__ int c_ndst[9] = {NB, NA, NG, NA, NG, NB, NA, NB, NG};
__constant__ int c_rl[9] = {1, 3, 6, 0, 5, 7, 2, 4, 8};
__constant__ int c_toff[3] = {0, NA, NA + NB};

// ---------------- device scratch ----------------
__device__ int g_odeg[DEG_TOT];
__device__ int g_ideg[DEG_TOT];
__device__ int g_offs[DEG_TOT];
__device__ int2 g_rowinfo[DEG_TOT];               // {csr_off (fill), deg (scan1)}
__device__ int g_cursor[DEG_TOT];
__device__ int g_bsum[SCAN_NB];
__device__ int2 g_epack[NE_TOT];                  // {src_byte_off, ns fp32 bits}
__device__ float g_ns[DEG_TOT];
__device__ float g_nd[DEG_TOT];
__device__ __align__(128) __half g_fh[(size_t)NTOT * D];
__device__ __align__(128) __half g_mh[(size_t)NTILES * 16384];
__device__ __align__(128) __half g_gout[(size_t)DEG_TOT * D];
__device__ float g_stats[9 * 2 * D];
__device__ float g_scale[9 * D];
__device__ float g_shift[9 * D];
__device__ __align__(128) __half g_wh[18 * D * D];

struct EdgePtrs { const int* s[9]; const int* d[9]; };

// ---------------- helpers ----------------
__device__ __forceinline__ uint32_t sw128(uint32_t o) { return o ^ ((o >> 3) & 0x70); }
__device__ __forceinline__ uint32_t toff128(uint32_t row, uint32_t k) {
    return ((k >> 6) << 14) + sw128(row * 128 + ((k & 63) << 1));
}
__device__ __forceinline__ uint32_t smem_u32(const void* p) {
    uint32_t a;
    asm("{ .reg .u64 t; cvta.to.shared.u64 t, %1; cvt.u32.u64 %0, t; }" : "=r"(a) : "l"(p));
    return a;
}
__device__ __forceinline__ void ldsm4(uint32_t& r0, uint32_t& r1, uint32_t& r2, uint32_t& r3,
                                      uint32_t addr) {
    asm volatile("ldmatrix.sync.aligned.m8n8.x4.shared.b16 {%0,%1,%2,%3}, [%4];"
                 : "=r"(r0), "=r"(r1), "=r"(r2), "=r"(r3) : "r"(addr));
}
__device__ __forceinline__ void mma_f16(float* d, const uint32_t* a, uint32_t b0, uint32_t b1) {
    asm volatile(
        "mma.sync.aligned.m16n8k16.row.col.f32.f16.f16.f32 "
        "{%0,%1,%2,%3}, {%4,%5,%6,%7}, {%8,%9}, {%0,%1,%2,%3};"
        : "+f"(d[0]), "+f"(d[1]), "+f"(d[2]), "+f"(d[3])
        : "r"(a[0]), "r"(a[1]), "r"(a[2]), "r"(a[3]), "r"(b0), "r"(b1));
}
__device__ __forceinline__ void cpasync16(uint32_t dst, const void* src) {
    asm volatile("cp.async.ca.shared.global [%0], [%1], 16;" :: "r"(dst), "l"(src));
}

// ---------------- launch 0: W->fp16 swizzled + degree count + feat->fp16 -------
__global__ void k_prep(EdgePtrs E, const float* __restrict__ W,
                       const float4* __restrict__ fa4, const float4* __restrict__ fb4,
                       const float4* __restrict__ fg4) {
    if (blockIdx.x < 18) {
        int rel = blockIdx.x;
        const float* w = W + (size_t)rel * D * D;
        char* wh = (char*)g_wh + (size_t)rel * D * D * 2;
        for (int idx = threadIdx.x; idx < D * D; idx += blockDim.x) {
            int k = idx >> 7, n = idx & 127;
            *(__half*)(wh + toff128(n, k)) = __float2half_rn(w[idx]);
        }
        return;
    }
    if (blockIdx.x < 18 + EBLK) {
        int e = (blockIdx.x - 18) * blockDim.x + threadIdx.x;
        if (e >= NE_TOT) return;
        int rel = 0;
#pragma unroll
        for (int r = 1; r < 9; r++) if (e >= c_eoff[r]) rel = r;
        int le = e - c_eoff[rel];
        atomicAdd(&g_odeg[c_soff[rel] + E.s[rel][le]], 1);
        atomicAdd(&g_ideg[c_doff[rel] + E.d[rel][le]], 1);
        return;
    }
    int i = (blockIdx.x - 18 - EBLK) * blockDim.x + threadIdx.x;
    if (i >= NTOT * 32) return;
    int t = (i < NA * 32) ? 0 : (i < (NA + NB) * 32) ? 1 : 2;
    const float4* src = (t == 0) ? fa4 : (t == 1) ? fb4 : fg4;
    int base4 = (t == 0) ? 0 : (t == 1) ? NA * 32 : (NA + NB) * 32;
    float4 v = src[i - base4];
    ((__half2*)g_fh)[i * 2] = __floats2half2_rn(v.x, v.y);
    ((__half2*)g_fh)[i * 2 + 1] = __floats2half2_rn(v.z, v.w);
}

// ---------------- launch 1: scan + ns/nd + rowinfo.deg + cursor/stats zero -----
__global__ void k_scan1() {
    int tid = threadIdx.x;
    int gid = blockIdx.x * 1024 + tid;
    int lane = tid & 31;
    int w = tid >> 5;
    int v = (gid < DEG_TOT) ? g_ideg[gid] : 0;
    if (gid < DEG_TOT) {
        int od = g_odeg[gid];
        g_ns[gid] = (od > 0) ? rsqrtf((float)od) : 0.f;
        g_nd[gid] = (v > 0) ? rsqrtf((float)v) : 0.f;
        g_cursor[gid] = 0;
        g_rowinfo[gid].y = v;
    }
    if (blockIdx.x == 0) {
        for (int i = tid; i < 9 * 256; i += 1024) g_stats[i] = 0.f;
    }
    int inc = v;
#pragma unroll
    for (int s = 1; s < 32; s <<= 1) {
        int x = __shfl_up_sync(0xffffffffu, inc, s);
        if (lane >= s) inc += x;
    }
    __shared__ int wsum[32];
    if (lane == 31) wsum[w] = inc;
    __syncthreads();
    if (w == 0) {
        int x = (lane < 32) ? wsum[lane] : 0;
        int sc = x;
#pragma unroll
        for (int s = 1; s < 32; s <<= 1) {
            int y = __shfl_up_sync(0xffffffffu, sc, s);
            if (lane >= s) sc += y;
        }
        wsum[lane] = sc - x;
    }
    __syncthreads();
    int excl = inc - v + wsum[w];
    if (gid < DEG_TOT) g_offs[gid] = excl;
    if (tid == 1023) g_bsum[blockIdx.x] = excl + v;
}

// ---------------- launch 2: CSR fill (writes rowinfo.off) ----------------
__global__ __launch_bounds__(256)
void k_fill_all(EdgePtrs E) {
    __shared__ int sb[768];
    __shared__ int wsum[8];
    int t = threadIdx.x;
    int base = t * 3;
    int a0 = (base < SCAN_NB) ? g_bsum[base] : 0;
    int a1 = (base + 1 < SCAN_NB) ? g_bsum[base + 1] : 0;
    int a2 = (base + 2 < SCAN_NB) ? g_bsum[base + 2] : 0;
    int tsum = a0 + a1 + a2;
    int lane = t & 31;
    int inc = tsum;
#pragma unroll
    for (int s = 1; s < 32; s <<= 1) {
        int x = __shfl_up_sync(0xffffffffu, inc, s);
        if (lane >= s) inc += x;
    }
    if (lane == 31) wsum[t >> 5] = inc;
    __syncthreads();
    if (t < 8) {
        int x = wsum[t];
        int sc = x;
#pragma unroll
        for (int s = 1; s < 8; s <<= 1) {
            int y = __shfl_up_sync(0xffu, sc, s);
            if (t >= s) sc += y;
        }
        wsum[t] = sc - x;
    }
    __syncthreads();
    int excl = inc - tsum + wsum[t >> 5];
    sb[base] = excl;
    sb[base + 1] = excl + a0;
    sb[base + 2] = excl + a0 + a1;
    __syncthreads();

    int e = blockIdx.x * blockDim.x + t;
    if (e >= NE_TOT) return;
    int rel = 0;
#pragma unroll
    for (int r = 1; r < 9; r++) if (e >= c_eoff[r]) rel = r;
    int le = e - c_eoff[rel];
    int ss = E.s[rel][le];
    int dd = E.d[rel][le];
    int gslot = c_doff[rel] + dd;
    int ofin = g_offs[gslot] + sb[gslot >> 10];
    int pos = ofin + atomicAdd(&g_cursor[gslot], 1);
    g_epack[pos] = make_int2(ss * 256, __float_as_int(g_ns[c_soff[rel] + ss]));
    g_rowinfo[gslot].x = ofin;
}

// ------ gather: 2 rows/warp (half-warp per row), fp32 accum -> fp16 A tiles ----
__global__ void k_gather_all(const __half* __restrict__ fh) {
    int lane = threadIdx.x & 31;
    int l16 = lane & 15;
    int row = (blockIdx.x * (blockDim.x >> 5) + (threadIdx.x >> 5)) * 2 + (lane >> 4);
    if (row >= DEG_TOT) return;
    int rel = 0;
#pragma unroll
    for (int r = 1; r < 9; r++) if (row >= c_doff[r]) rel = r;
    int lrow = row - c_doff[rel];
    const char* fbase = (const char*)fh + (size_t)c_stoff[rel] * 256 + l16 * 16;

    int2 ri = __ldg(&g_rowinfo[row]);
    int dg = ri.y;
    float acc[8];
#pragma unroll
    for (int j = 0; j < 8; j++) acc[j] = 0.f;
    if (dg > 0) {
        const int2* ep = g_epack + ri.x;
        int e = 0;
        for (; e + 2 <= dg; e += 2) {
            int2 p0 = __ldg(ep + e);
            int2 p1 = __ldg(ep + e + 1);
            uint4 v0 = __ldg((const uint4*)(fbase + (uint32_t)p0.x));
            uint4 v1 = __ldg((const uint4*)(fbase + (uint32_t)p1.x));
            float w0 = __int_as_float(p0.y), w1 = __int_as_float(p1.y);
            float2 a0 = __half22float2(*(__half2*)&v0.x), b0 = __half22float2(*(__half2*)&v1.x);
            float2 a1 = __half22float2(*(__half2*)&v0.y), b1 = __half22float2(*(__half2*)&v1.y);
            float2 a2 = __half22float2(*(__half2*)&v0.z), b2 = __half22float2(*(__half2*)&v1.z);
            float2 a3 = __half22float2(*(__half2*)&v0.w), b3 = __half22float2(*(__half2*)&v1.w);
            acc[0] += a0.x * w0 + b0.x * w1;
            acc[1] += a0.y * w0 + b0.y * w1;
            acc[2] += a1.x * w0 + b1.x * w1;
            acc[3] += a1.y * w0 + b1.y * w1;
            acc[4] += a2.x * w0 + b2.x * w1;
            acc[5] += a2.y * w0 + b2.y * w1;
            acc[6] += a3.x * w0 + b3.x * w1;
            acc[7] += a3.y * w0 + b3.y * w1;
        }
        if (e < dg) {
            int2 p0 = __ldg(ep + e);
            uint4 v0 = __ldg((const uint4*)(fbase + (uint32_t)p0.x));
            float w0 = __int_as_float(p0.y);
            float2 a0 = __half22float2(*(__half2*)&v0.x);
            float2 a1 = __half22float2(*(__half2*)&v0.y);
            float2 a2 = __half22float2(*(__half2*)&v0.z);
            float2 a3 = __half22float2(*(__half2*)&v0.w);
            acc[0] += a0.x * w0; acc[1] += a0.y * w0;
            acc[2] += a1.x * w0; acc[3] += a1.y * w0;
            acc[4] += a2.x * w0; acc[5] += a2.y * w0;
            acc[6] += a3.x * w0; acc[7] += a3.y * w0;
        }
        float ndv = __ldg(g_nd + row);
#pragma unroll
        for (int j = 0; j < 8; j++) acc[j] *= ndv;
    }

    uint4 packed;
    *(__half2*)&packed.x = __floats2half2_rn(acc[0], acc[1]);
    *(__half2*)&packed.y = __floats2half2_rn(acc[2], acc[3]);
    *(__half2*)&packed.z = __floats2half2_rn(acc[4], acc[5]);
    *(__half2*)&packed.w = __floats2half2_rn(acc[6], acc[7]);

    size_t tile = (size_t)c_tbase[rel] + (lrow >> 7);
    uint32_t ir = lrow & 127;
    char* bh = (char*)g_mh + tile * 32768;
    uint32_t o = ((uint32_t)(l16 >> 3) << 14) + sw128(ir * 128 + (l16 & 7) * 16);
    *(uint4*)(bh + o) = packed;
}

// ---------------- batched GEMM (single fp16 product) + stats ----------------
#define OFF_A    0
#define OFF_B    32768
#define OFF_STAT 65536
#define SMEM_DYN (65536 + 1024 + 1024)

__global__ __launch_bounds__(256, 2)
void k_gemm_all(const __half* __restrict__ mh, const __half* __restrict__ whAll,
                int layer, __half* __restrict__ out, float* __restrict__ stats) {
    extern __shared__ char smem_raw[];
    char* smem = (char*)((((uintptr_t)smem_raw) + 1023) & ~(uintptr_t)1023);
    uint32_t sa = smem_u32(smem);
    int tid = threadIdx.x;
    int lane = tid & 31;
    int wid = tid >> 5;
    int bid = blockIdx.x;

    int rel = 0;
#pragma unroll
    for (int r = 1; r < 9; r++) if (bid >= c_tbase[r]) rel = r;
    int rowBase = (bid - c_tbase[rel]) * 128;
    int ndst = c_doff[rel + 1] - c_doff[rel];
    int goutBase = c_doff[rel];

    ((float*)(smem + OFF_STAT))[tid] = 0.f;
    {
        const char* sA = (const char*)mh + (size_t)bid * 32768;
        const char* sB = (const char*)whAll + (size_t)(layer * 9 + rel) * 32768;
#pragma unroll
        for (int i = tid; i < 2048; i += 256) {
            cpasync16(sa + OFF_A + i * 16, sA + i * 16);
            cpasync16(sa + OFF_B + i * 16, sB + i * 16);
        }
        asm volatile("cp.async.commit_group;" ::: "memory");
        asm volatile("cp.async.wait_group 0;" ::: "memory");
    }
    __syncthreads();

    float acc[16][4];
#pragma unroll
    for (int t = 0; t < 16; t++)
#pragma unroll
        for (int j = 0; j < 4; j++) acc[t][j] = 0.f;

    int m0 = wid * 16;
    uint32_t rowA = m0 + (lane & 15);
    uint32_t kA = (lane >> 4) << 3;
    uint32_t rowB = (lane & 7) + ((lane >> 4) << 3);
    uint32_t kB = ((lane >> 3) & 1) << 3;

    uint32_t ab = sa + OFF_A;
    uint32_t bb = sa + OFF_B;
#pragma unroll
    for (int k0 = 0; k0 < 128; k0 += 16) {
        uint32_t a[4];
        ldsm4(a[0], a[1], a[2], a[3], ab + toff128(rowA, k0 + kA));
#pragma unroll
        for (int nn = 0; nn < 8; nn++) {
            uint32_t b0, b1, b2, b3;
            ldsm4(b0, b1, b2, b3, bb + toff128(nn * 16 + rowB, k0 + kB));
            mma_f16(acc[2 * nn], a, b0, b1);
            mma_f16(acc[2 * nn + 1], a, b2, b3);
        }
    }

    int quad = lane >> 2;
    int cp = (lane & 3) * 2;
    int lr0 = rowBase + m0 + quad;
    int lr1 = lr0 + 8;
    bool v0 = lr0 < ndst, v1 = lr1 < ndst;
    float* sstat = (float*)(smem + OFF_STAT);

#pragma unroll
    for (int t = 0; t < 16; t++) {
        int c = t * 8 + cp;
        float x0 = acc[t][0], x1 = acc[t][1];
        float y0 = acc[t][2], y1 = acc[t][3];
        if (v0) *(__half2*)(out + (size_t)(goutBase + lr0) * D + c) = __floats2half2_rn(x0, x1);
        if (v1) *(__half2*)(out + (size_t)(goutBase + lr1) * D + c) = __floats2half2_rn(y0, y1);
        float s0 = (v0 ? x0 : 0.f) + (v1 ? y0 : 0.f);
        float s1 = (v0 ? x1 : 0.f) + (v1 ? y1 : 0.f);
        float q0 = (v0 ? x0 * x0 : 0.f) + (v1 ? y0 * y0 : 0.f);
        float q1 = (v0 ? x1 * x1 : 0.f) + (v1 ? y1 * y1 : 0.f);
#pragma unroll
        for (int S = 4; S <= 16; S <<= 1) {
            s0 += __shfl_xor_sync(0xffffffffu, s0, S);
            s1 += __shfl_xor_sync(0xffffffffu, s1, S);
            q0 += __shfl_xor_sync(0xffffffffu, q0, S);
            q1 += __shfl_xor_sync(0xffffffffu, q1, S);
        }
        if (lane < 4) {
            atomicAdd(&sstat[c], s0);
            atomicAdd(&sstat[c + 1], s1);
            atomicAdd(&sstat[128 + c], q0);
            atomicAdd(&sstat[128 + c + 1], q1);
        }
    }
    __syncthreads();
    atomicAdd(&stats[rel * 256 + tid], sstat[tid]);
}

// ---------------- BN finalize (re-zeroes stats for next layer) ----------------
__global__ void k_finalize9(const float* __restrict__ gammaL, const float* __restrict__ betaL) {
    int r = blockIdx.x;
    int c = threadIdx.x;
    float n = (float)c_ndst[r];
    float mu = g_stats[r * 256 + c] / n;
    float var = g_stats[r * 256 + 128 + c] / n - mu * mu;
    float inv = rsqrtf(var + BN_EPS);
    float sc = inv * gammaL[r * D + c];
    g_scale[r * D + c] = sc;
    g_shift[r * D + c] = betaL[r * D + c] - mu * sc;
    g_stats[r * 256 + c] = 0.f;
    g_stats[r * 256 + 128 + c] = 0.f;
}

// ------- fused normalize + 3-rel sum; layer0 -> fp16 feat, layer1 -> fp32 out ---
__global__ void k_fuse_all(const __half* __restrict__ gout,
                           const float4* __restrict__ ra, const float4* __restrict__ rb,
                           const float4* __restrict__ rg, int layer,
                           float4* __restrict__ outF, __half* __restrict__ outH) {
    int i = blockIdx.x * blockDim.x + threadIdx.x;
    if (i >= NTOT * 32) return;
    int row = i >> 5;
    int c4 = i & 31;
    int c = c4 * 4;
    int type = (row < NA) ? 0 : (row < NA + NB) ? 1 : 2;
    int local = row - c_toff[type];
    int r0 = c_rl[type * 3], r1 = c_rl[type * 3 + 1], r2 = c_rl[type * 3 + 2];

    uint2 ha = *(const uint2*)(gout + (size_t)(c_doff[r0] + local) * D + c);
    uint2 hb = *(const uint2*)(gout + (size_t)(c_doff[r1] + local) * D + c);
    uint2 hg = *(const uint2*)(gout + (size_t)(c_doff[r2] + local) * D + c);
    float2 a01 = __half22float2(*(__half2*)&ha.x), a23 = __half22float2(*(__half2*)&ha.y);
    float2 b01 = __half22float2(*(__half2*)&hb.x), b23 = __half22float2(*(__half2*)&hb.y);
    float2 g01 = __half22float2(*(__half2*)&hg.x), g23 = __half22float2(*(__half2*)&hg.y);

    float4 o;
    o.x = a01.x * g_scale[r0 * D + c + 0] + b01.x * g_scale[r1 * D + c + 0] + g01.x * g_scale[r2 * D + c + 0]
        + g_shift[r0 * D + c + 0] + g_shift[r1 * D + c + 0] + g_shift[r2 * D + c + 0];
    o.y = a01.y * g_scale[r0 * D + c + 1] + b01.y * g_scale[r1 * D + c + 1] + g01.y * g_scale[r2 * D + c + 1]
        + g_shift[r0 * D + c + 1] + g_shift[r1 * D + c + 1] + g_shift[r2 * D + c + 1];
    o.z = a23.x * g_scale[r0 * D + c + 2] + b23.x * g_scale[r1 * D + c + 2] + g23.x * g_scale[r2 * D + c + 2]
        + g_shift[r0 * D + c + 2] + g_shift[r1 * D + c + 2] + g_shift[r2 * D + c + 2];
    o.w = a23.y * g_scale[r0 * D + c + 3] + b23.y * g_scale[r1 * D + c + 3] + g23.y * g_scale[r2 * D + c + 3]
        + g_shift[r0 * D + c + 3] + g_shift[r1 * D + c + 3] + g_shift[r2 * D + c + 3];
    if (layer == 1) {
        const float4* rp = (type == 0) ? ra : (type == 1) ? rb : rg;
        float4 rr = rp[(size_t)local * 32 + c4];
        o.x += rr.x; o.y += rr.y; o.z += rr.z; o.w += rr.w;
        outF[i] = o;
    } else {
        ((__half2*)outH)[i * 2] = __floats2half2_rn(o.x, o.y);
        ((__half2*)outH)[i * 2 + 1] = __floats2half2_rn(o.z, o.w);
    }
}

// ---------------- cleanup ----------------
__global__ void k_cleanup() {
    int i = blockIdx.x * blockDim.x + threadIdx.x;
    int n4 = DEG_TOT / 4;
    if (i < n4) {
        ((int4*)g_odeg)[i] = make_int4(0, 0, 0, 0);
        ((int4*)g_ideg)[i] = make_int4(0, 0, 0, 0);
    }
}

// ---------------- host orchestration ----------------
static inline int cdiv(int a, int b) { return (a + b - 1) / b; }

extern "C" void kernel_launch(void* const* d_in, const int* in_sizes, int n_in,
                              void* d_out, int out_size) {
    const float* fa = (const float*)d_in[0];
    const float* fb = (const float*)d_in[1];
    const float* fg = (const float*)d_in[2];
    const float* W = (const float*)d_in[3];
    const float* gamma = (const float*)d_in[5];
    const float* beta = (const float*)d_in[6];

    EdgePtrs E;
    for (int r = 0; r < 9; r++) {
        E.s[r] = (const int*)d_in[7 + 2 * r];
        E.d[r] = (const int*)d_in[8 + 2 * r];
    }

    float* p_stats;
    __half *p_wh, *p_mh, *p_fh, *p_gout;
    cudaGetSymbolAddress((void**)&p_gout, g_gout);
    cudaGetSymbolAddress((void**)&p_stats, g_stats);
    cudaGetSymbolAddress((void**)&p_wh, g_wh);
    cudaGetSymbolAddress((void**)&p_mh, g_mh);
    cudaGetSymbolAddress((void**)&p_fh, g_fh);

    cudaFuncSetAttribute(k_gemm_all, cudaFuncAttributeMaxDynamicSharedMemorySize, SMEM_DYN);

    const int TB = 256;
    const int GGRID = DEG_TOT / 16;   // 2 rows per warp, 8 warps per block

    // 0: W->fp16 + degree count + feat->fp16
    k_prep<<<18 + EBLK + CBLK, TB>>>(E, W, (const float4*)fa, (const float4*)fb,
                                     (const float4*)fg);
    // 1: scan + ns/nd + rowinfo.deg
    k_scan1<<<SCAN_NB, 1024>>>();
    // 2: CSR fill (rowinfo.off)
    k_fill_all<<<cdiv(NE_TOT, TB), TB>>>(E);
    // 3: gather L0 (ncu target)
    k_gather_all<<<GGRID, TB>>>(p_fh);
    // 4: GEMM L0
    k_gemm_all<<<NTILES, 256, SMEM_DYN>>>(p_mh, p_wh, 0, p_gout, p_stats);
    // 5: finalize L0
    k_finalize9<<<9, 128>>>(gamma, beta);
    // 6: fuse L0 -> fp16 feat
    k_fuse_all<<<cdiv(NTOT * 32, TB), TB>>>(p_gout, (const float4*)fa, (const float4*)fb,
                                            (const float4*)fg, 0, nullptr, p_fh);
    // 7-10: layer 1
    k_gather_all<<<GGRID, TB>>>(p_fh);
    k_gemm_all<<<NTILES, 256, SMEM_DYN>>>(p_mh, p_wh, 1, p_gout, p_stats);
    k_finalize9<<<9, 128>>>(gamma + 9 * D, beta + 9 * D);
    k_fuse_all<<<cdiv(NTOT * 32, TB), TB>>>(p_gout, (const float4*)fa, (const float4*)fb,
                                            (const float4*)fg, 1, (float4*)d_out, nullptr);
    // 11: cleanup
    k_cleanup<<<cdiv(DEG_TOT / 4, TB), TB>>>();
}

// round 13
// speedup vs baseline: 2.4969x; 1.0522x over previous
#include <cuda_runtime.h>
#include <cuda_fp16.h>
#include <cstdint>

#define D 128
#define NA 100000
#define NB 150000
#define NG 2000
#define NTOT (NA + NB + NG)      // 252000
#define DEG_TOT 756000
#define NE_TOT 1352000
#define NTILES 5910
#define BN_EPS 1e-5f
#define SCAN_NB ((DEG_TOT + 1023) / 1024)   // 739

#define EBLK ((NE_TOT + 255) / 256)          // 5282
#define CBLK ((NTOT * 32 + 255) / 256)       // 31500

// ---------------- constant boundary tables ----------------
__constant__ int c_doff[10] = {0,150000,250000,252000,352000,354000,504000,604000,754000,756000};
__constant__ int c_soff[10] = {0,100000,250000,350000,352000,502000,504000,604000,754000,756000};
__constant__ int c_eoff[10] = {0,300000,600000,700000,800000,950000,1100000,1200000,1350000,1352000};
__constant__ int c_tbase[10] = {0,1172,1954,1970,2752,2768,3940,4722,5894,5910};
__constant__ int c_stoff[9] = {0, NA, 0, NA + NB, NA, NA + NB, 0, NA, NA + NB};
__constant__ int c_ndst[9] = {NB, NA, NG, NA, NG, NB, NA, NB, NG};
__constant__ int c_rl[9] = {1, 3, 6, 0, 5, 7, 2, 4, 8};
__constant__ int c_toff[3] = {0, NA, NA + NB};

// ---------------- device scratch ----------------
__device__ int g_odeg[DEG_TOT];
__device__ int g_ideg[DEG_TOT];
__device__ int g_offs[DEG_TOT];
__device__ int2 g_rowinfo[DEG_TOT];               // {csr_off (fill), deg (scan1)}
__device__ int g_cursor[DEG_TOT];
__device__ int g_bsum[SCAN_NB];
__device__ int2 g_epack[NE_TOT];                  // {src_byte_off, ns fp32 bits}
__device__ float g_ns[DEG_TOT];
__device__ float g_nd[DEG_TOT];
__device__ __align__(128) __half g_fh[(size_t)NTOT * D];
__device__ __align__(128) __half g_mh[(size_t)NTILES * 16384];
__device__ __align__(128) __half g_gout[(size_t)DEG_TOT * D];
__device__ float g_stats[9 * 2 * D];
__device__ float g_scale[9 * D];
__device__ float g_shift[9 * D];
__device__ __align__(128) __half g_wh[18 * D * D];

struct EdgePtrs { const int* s[9]; const int* d[9]; };

// ---------------- helpers ----------------
__device__ __forceinline__ uint32_t sw128(uint32_t o) { return o ^ ((o >> 3) & 0x70); }
__device__ __forceinline__ uint32_t toff128(uint32_t row, uint32_t k) {
    return ((k >> 6) << 14) + sw128(row * 128 + ((k & 63) << 1));
}
__device__ __forceinline__ uint32_t smem_u32(const void* p) {
    uint32_t a;
    asm("{ .reg .u64 t; cvta.to.shared.u64 t, %1; cvt.u32.u64 %0, t; }" : "=r"(a) : "l"(p));
    return a;
}
__device__ __forceinline__ void ldsm4(uint32_t& r0, uint32_t& r1, uint32_t& r2, uint32_t& r3,
                                      uint32_t addr) {
    asm volatile("ldmatrix.sync.aligned.m8n8.x4.shared.b16 {%0,%1,%2,%3}, [%4];"
                 : "=r"(r0), "=r"(r1), "=r"(r2), "=r"(r3) : "r"(addr));
}
__device__ __forceinline__ void mma_f16(float* d, const uint32_t* a, uint32_t b0, uint32_t b1) {
    asm volatile(
        "mma.sync.aligned.m16n8k16.row.col.f32.f16.f16.f32 "
        "{%0,%1,%2,%3}, {%4,%5,%6,%7}, {%8,%9}, {%0,%1,%2,%3};"
        : "+f"(d[0]), "+f"(d[1]), "+f"(d[2]), "+f"(d[3])
        : "r"(a[0]), "r"(a[1]), "r"(a[2]), "r"(a[3]), "r"(b0), "r"(b1));
}
__device__ __forceinline__ void cpasync16(uint32_t dst, const void* src) {
    asm volatile("cp.async.ca.shared.global [%0], [%1], 16;" :: "r"(dst), "l"(src));
}
__device__ __forceinline__ void acc8(float* acc, const uint4& v, float w) {
    float2 t0 = __half22float2(*(__half2*)&v.x);
    float2 t1 = __half22float2(*(__half2*)&v.y);
    float2 t2 = __half22float2(*(__half2*)&v.z);
    float2 t3 = __half22float2(*(__half2*)&v.w);
    acc[0] += t0.x * w; acc[1] += t0.y * w;
    acc[2] += t1.x * w; acc[3] += t1.y * w;
    acc[4] += t2.x * w; acc[5] += t2.y * w;
    acc[6] += t3.x * w; acc[7] += t3.y * w;
}

// ---------------- launch 0: W->fp16 swizzled + degree count + feat->fp16 -------
__global__ void k_prep(EdgePtrs E, const float* __restrict__ W,
                       const float4* __restrict__ fa4, const float4* __restrict__ fb4,
                       const float4* __restrict__ fg4) {
    if (blockIdx.x < 18) {
        int rel = blockIdx.x;
        const float* w = W + (size_t)rel * D * D;
        char* wh = (char*)g_wh + (size_t)rel * D * D * 2;
        for (int idx = threadIdx.x; idx < D * D; idx += blockDim.x) {
            int k = idx >> 7, n = idx & 127;
            *(__half*)(wh + toff128(n, k)) = __float2half_rn(w[idx]);
        }
        return;
    }
    if (blockIdx.x < 18 + EBLK) {
        int e = (blockIdx.x - 18) * blockDim.x + threadIdx.x;
        if (e >= NE_TOT) return;
        int rel = 0;
#pragma unroll
        for (int r = 1; r < 9; r++) if (e >= c_eoff[r]) rel = r;
        int le = e - c_eoff[rel];
        atomicAdd(&g_odeg[c_soff[rel] + E.s[rel][le]], 1);
        atomicAdd(&g_ideg[c_doff[rel] + E.d[rel][le]], 1);
        return;
    }
    int i = (blockIdx.x - 18 - EBLK) * blockDim.x + threadIdx.x;
    if (i >= NTOT * 32) return;
    int t = (i < NA * 32) ? 0 : (i < (NA + NB) * 32) ? 1 : 2;
    const float4* src = (t == 0) ? fa4 : (t == 1) ? fb4 : fg4;
    int base4 = (t == 0) ? 0 : (t == 1) ? NA * 32 : (NA + NB) * 32;
    float4 v = src[i - base4];
    ((__half2*)g_fh)[i * 2] = __floats2half2_rn(v.x, v.y);
    ((__half2*)g_fh)[i * 2 + 1] = __floats2half2_rn(v.z, v.w);
}

// ---------------- launch 1: scan + ns/nd + rowinfo.deg + cursor/stats zero -----
__global__ void k_scan1() {
    int tid = threadIdx.x;
    int gid = blockIdx.x * 1024 + tid;
    int lane = tid & 31;
    int w = tid >> 5;
    int v = (gid < DEG_TOT) ? g_ideg[gid] : 0;
    if (gid < DEG_TOT) {
        int od = g_odeg[gid];
        g_ns[gid] = (od > 0) ? rsqrtf((float)od) : 0.f;
        g_nd[gid] = (v > 0) ? rsqrtf((float)v) : 0.f;
        g_cursor[gid] = 0;
        g_rowinfo[gid].y = v;
    }
    if (blockIdx.x == 0) {
        for (int i = tid; i < 9 * 256; i += 1024) g_stats[i] = 0.f;
    }
    int inc = v;
#pragma unroll
    for (int s = 1; s < 32; s <<= 1) {
        int x = __shfl_up_sync(0xffffffffu, inc, s);
        if (lane >= s) inc += x;
    }
    __shared__ int wsum[32];
    if (lane == 31) wsum[w] = inc;
    __syncthreads();
    if (w == 0) {
        int x = (lane < 32) ? wsum[lane] : 0;
        int sc = x;
#pragma unroll
        for (int s = 1; s < 32; s <<= 1) {
            int y = __shfl_up_sync(0xffffffffu, sc, s);
            if (lane >= s) sc += y;
        }
        wsum[lane] = sc - x;
    }
    __syncthreads();
    int excl = inc - v + wsum[w];
    if (gid < DEG_TOT) g_offs[gid] = excl;
    if (tid == 1023) g_bsum[blockIdx.x] = excl + v;
}

// ---------------- launch 2: CSR fill (writes rowinfo.off) ----------------
__global__ __launch_bounds__(256)
void k_fill_all(EdgePtrs E) {
    __shared__ int sb[768];
    __shared__ int wsum[8];
    int t = threadIdx.x;
    int base = t * 3;
    int a0 = (base < SCAN_NB) ? g_bsum[base] : 0;
    int a1 = (base + 1 < SCAN_NB) ? g_bsum[base + 1] : 0;
    int a2 = (base + 2 < SCAN_NB) ? g_bsum[base + 2] : 0;
    int tsum = a0 + a1 + a2;
    int lane = t & 31;
    int inc = tsum;
#pragma unroll
    for (int s = 1; s < 32; s <<= 1) {
        int x = __shfl_up_sync(0xffffffffu, inc, s);
        if (lane >= s) inc += x;
    }
    if (lane == 31) wsum[t >> 5] = inc;
    __syncthreads();
    if (t < 8) {
        int x = wsum[t];
        int sc = x;
#pragma unroll
        for (int s = 1; s < 8; s <<= 1) {
            int y = __shfl_up_sync(0xffu, sc, s);
            if (t >= s) sc += y;
        }
        wsum[t] = sc - x;
    }
    __syncthreads();
    int excl = inc - tsum + wsum[t >> 5];
    sb[base] = excl;
    sb[base + 1] = excl + a0;
    sb[base + 2] = excl + a0 + a1;
    __syncthreads();

    int e = blockIdx.x * blockDim.x + t;
    if (e >= NE_TOT) return;
    int rel = 0;
#pragma unroll
    for (int r = 1; r < 9; r++) if (e >= c_eoff[r]) rel = r;
    int le = e - c_eoff[rel];
    int ss = E.s[rel][le];
    int dd = E.d[rel][le];
    int gslot = c_doff[rel] + dd;
    int ofin = g_offs[gslot] + sb[gslot >> 10];
    int pos = ofin + atomicAdd(&g_cursor[gslot], 1);
    g_epack[pos] = make_int2(ss * 256, __float_as_int(g_ns[c_soff[rel] + ss]));
    g_rowinfo[gslot].x = ofin;
}

// ------ gather: 4 rows/warp (8 lanes/row, 32B/lane), fp32 accum -> fp16 tiles ---
__global__ void k_gather_all(const __half* __restrict__ fh) {
    int lane = threadIdx.x & 31;
    int l8 = lane & 7;
    int row = (blockIdx.x * (blockDim.x >> 5) + (threadIdx.x >> 5)) * 4 + (lane >> 3);
    if (row >= DEG_TOT) return;
    int rel = 0;
#pragma unroll
    for (int r = 1; r < 9; r++) if (row >= c_doff[r]) rel = r;
    int lrow = row - c_doff[rel];
    const char* fbase = (const char*)fh + (size_t)c_stoff[rel] * 256 + l8 * 32;

    int2 ri = __ldg(&g_rowinfo[row]);
    int dg = ri.y;
    float acc[16];
#pragma unroll
    for (int j = 0; j < 16; j++) acc[j] = 0.f;
    if (dg > 0) {
        const int2* ep = g_epack + ri.x;
        int e = 0;
        for (; e + 2 <= dg; e += 2) {
            int2 p0 = __ldg(ep + e);
            int2 p1 = __ldg(ep + e + 1);
            uint4 v0a = __ldg((const uint4*)(fbase + (uint32_t)p0.x));
            uint4 v0b = __ldg((const uint4*)(fbase + (uint32_t)p0.x + 16));
            uint4 v1a = __ldg((const uint4*)(fbase + (uint32_t)p1.x));
            uint4 v1b = __ldg((const uint4*)(fbase + (uint32_t)p1.x + 16));
            float w0 = __int_as_float(p0.y), w1 = __int_as_float(p1.y);
            acc8(acc, v0a, w0);
            acc8(acc + 8, v0b, w0);
            acc8(acc, v1a, w1);
            acc8(acc + 8, v1b, w1);
        }
        if (e < dg) {
            int2 p0 = __ldg(ep + e);
            uint4 v0a = __ldg((const uint4*)(fbase + (uint32_t)p0.x));
            uint4 v0b = __ldg((const uint4*)(fbase + (uint32_t)p0.x + 16));
            float w0 = __int_as_float(p0.y);
            acc8(acc, v0a, w0);
            acc8(acc + 8, v0b, w0);
        }
        float ndv = __ldg(g_nd + row);
#pragma unroll
        for (int j = 0; j < 16; j++) acc[j] *= ndv;
    }

    uint4 pk0, pk1;
    *(__half2*)&pk0.x = __floats2half2_rn(acc[0], acc[1]);
    *(__half2*)&pk0.y = __floats2half2_rn(acc[2], acc[3]);
    *(__half2*)&pk0.z = __floats2half2_rn(acc[4], acc[5]);
    *(__half2*)&pk0.w = __floats2half2_rn(acc[6], acc[7]);
    *(__half2*)&pk1.x = __floats2half2_rn(acc[8], acc[9]);
    *(__half2*)&pk1.y = __floats2half2_rn(acc[10], acc[11]);
    *(__half2*)&pk1.z = __floats2half2_rn(acc[12], acc[13]);
    *(__half2*)&pk1.w = __floats2half2_rn(acc[14], acc[15]);

    size_t tile = (size_t)c_tbase[rel] + (lrow >> 7);
    uint32_t ir = lrow & 127;
    char* bh = (char*)g_mh + tile * 32768;
    uint32_t half_tile = (uint32_t)(l8 >> 2) << 14;
    uint32_t base = ir * 128 + (l8 & 3) * 32;
    *(uint4*)(bh + half_tile + sw128(base)) = pk0;
    *(uint4*)(bh + half_tile + sw128(base + 16)) = pk1;
}

// ---------------- batched GEMM (single fp16 product) + stats ----------------
#define OFF_A    0
#define OFF_B    32768
#define OFF_STAT 65536
#define SMEM_DYN (65536 + 1024 + 1024)

__global__ __launch_bounds__(256, 2)
void k_gemm_all(const __half* __restrict__ mh, const __half* __restrict__ whAll,
                int layer, __half* __restrict__ out, float* __restrict__ stats) {
    extern __shared__ char smem_raw[];
    char* smem = (char*)((((uintptr_t)smem_raw) + 1023) & ~(uintptr_t)1023);
    uint32_t sa = smem_u32(smem);
    int tid = threadIdx.x;
    int lane = tid & 31;
    int wid = tid >> 5;
    int bid = blockIdx.x;

    int rel = 0;
#pragma unroll
    for (int r = 1; r < 9; r++) if (bid >= c_tbase[r]) rel = r;
    int rowBase = (bid - c_tbase[rel]) * 128;
    int ndst = c_doff[rel + 1] - c_doff[rel];
    int goutBase = c_doff[rel];

    ((float*)(smem + OFF_STAT))[tid] = 0.f;
    {
        const char* sA = (const char*)mh + (size_t)bid * 32768;
        const char* sB = (const char*)whAll + (size_t)(layer * 9 + rel) * 32768;
#pragma unroll
        for (int i = tid; i < 2048; i += 256) {
            cpasync16(sa + OFF_A + i * 16, sA + i * 16);
            cpasync16(sa + OFF_B + i * 16, sB + i * 16);
        }
        asm volatile("cp.async.commit_group;" ::: "memory");
        asm volatile("cp.async.wait_group 0;" ::: "memory");
    }
    __syncthreads();

    float acc[16][4];
#pragma unroll
    for (int t = 0; t < 16; t++)
#pragma unroll
        for (int j = 0; j < 4; j++) acc[t][j] = 0.f;

    int m0 = wid * 16;
    uint32_t rowA = m0 + (lane & 15);
    uint32_t kA = (lane >> 4) << 3;
    uint32_t rowB = (lane & 7) + ((lane >> 4) << 3);
    uint32_t kB = ((lane >> 3) & 1) << 3;

    uint32_t ab = sa + OFF_A;
    uint32_t bb = sa + OFF_B;
#pragma unroll
    for (int k0 = 0; k0 < 128; k0 += 16) {
        uint32_t a[4];
        ldsm4(a[0], a[1], a[2], a[3], ab + toff128(rowA, k0 + kA));
#pragma unroll
        for (int nn = 0; nn < 8; nn++) {
            uint32_t b0, b1, b2, b3;
            ldsm4(b0, b1, b2, b3, bb + toff128(nn * 16 + rowB, k0 + kB));
            mma_f16(acc[2 * nn], a, b0, b1);
            mma_f16(acc[2 * nn + 1], a, b2, b3);
        }
    }

    int quad = lane >> 2;
    int cp = (lane & 3) * 2;
    int lr0 = rowBase + m0 + quad;
    int lr1 = lr0 + 8;
    bool v0 = lr0 < ndst, v1 = lr1 < ndst;
    float* sstat = (float*)(smem + OFF_STAT);

#pragma unroll
    for (int t = 0; t < 16; t++) {
        int c = t * 8 + cp;
        float x0 = acc[t][0], x1 = acc[t][1];
        float y0 = acc[t][2], y1 = acc[t][3];
        if (v0) *(__half2*)(out + (size_t)(goutBase + lr0) * D + c) = __floats2half2_rn(x0, x1);
        if (v1) *(__half2*)(out + (size_t)(goutBase + lr1) * D + c) = __floats2half2_rn(y0, y1);
        float s0 = (v0 ? x0 : 0.f) + (v1 ? y0 : 0.f);
        float s1 = (v0 ? x1 : 0.f) + (v1 ? y1 : 0.f);
        float q0 = (v0 ? x0 * x0 : 0.f) + (v1 ? y0 * y0 : 0.f);
        float q1 = (v0 ? x1 * x1 : 0.f) + (v1 ? y1 * y1 : 0.f);
#pragma unroll
        for (int S = 4; S <= 16; S <<= 1) {
            s0 += __shfl_xor_sync(0xffffffffu, s0, S);
            s1 += __shfl_xor_sync(0xffffffffu, s1, S);
            q0 += __shfl_xor_sync(0xffffffffu, q0, S);
            q1 += __shfl_xor_sync(0xffffffffu, q1, S);
        }
        if (lane < 4) {
            atomicAdd(&sstat[c], s0);
            atomicAdd(&sstat[c + 1], s1);
            atomicAdd(&sstat[128 + c], q0);
            atomicAdd(&sstat[128 + c + 1], q1);
        }
    }
    __syncthreads();
    atomicAdd(&stats[rel * 256 + tid], sstat[tid]);
}

// ---------------- BN finalize (re-zeroes stats for next layer) ----------------
__global__ void k_finalize9(const float* __restrict__ gammaL, const float* __restrict__ betaL) {
    int r = blockIdx.x;
    int c = threadIdx.x;
    float n = (float)c_ndst[r];
    float mu = g_stats[r * 256 + c] / n;
    float var = g_stats[r * 256 + 128 + c] / n - mu * mu;
    float inv = rsqrtf(var + BN_EPS);
    float sc = inv * gammaL[r * D + c];
    g_scale[r * D + c] = sc;
    g_shift[r * D + c] = betaL[r * D + c] - mu * sc;
    g_stats[r * 256 + c] = 0.f;
    g_stats[r * 256 + 128 + c] = 0.f;
}

// ------- fused normalize + 3-rel sum; layer0 -> fp16 feat, layer1 -> fp32 out ---
__global__ void k_fuse_all(const __half* __restrict__ gout,
                           const float4* __restrict__ ra, const float4* __restrict__ rb,
                           const float4* __restrict__ rg, int layer,
                           float4* __restrict__ outF, __half* __restrict__ outH) {
    int i = blockIdx.x * blockDim.x + threadIdx.x;
    if (i >= NTOT * 32) return;
    int row = i >> 5;
    int c4 = i & 31;
    int c = c4 * 4;
    int type = (row < NA) ? 0 : (row < NA + NB) ? 1 : 2;
    int local = row - c_toff[type];
    int r0 = c_rl[type * 3], r1 = c_rl[type * 3 + 1], r2 = c_rl[type * 3 + 2];

    uint2 ha = *(const uint2*)(gout + (size_t)(c_doff[r0] + local) * D + c);
    uint2 hb = *(const uint2*)(gout + (size_t)(c_doff[r1] + local) * D + c);
    uint2 hg = *(const uint2*)(gout + (size_t)(c_doff[r2] + local) * D + c);
    float2 a01 = __half22float2(*(__half2*)&ha.x), a23 = __half22float2(*(__half2*)&ha.y);
    float2 b01 = __half22float2(*(__half2*)&hb.x), b23 = __half22float2(*(__half2*)&hb.y);
    float2 g01 = __half22float2(*(__half2*)&hg.x), g23 = __half22float2(*(__half2*)&hg.y);

    float4 o;
    o.x = a01.x * g_scale[r0 * D + c + 0] + b01.x * g_scale[r1 * D + c + 0] + g01.x * g_scale[r2 * D + c + 0]
        + g_shift[r0 * D + c + 0] + g_shift[r1 * D + c + 0] + g_shift[r2 * D + c + 0];
    o.y = a01.y * g_scale[r0 * D + c + 1] + b01.y * g_scale[r1 * D + c + 1] + g01.y * g_scale[r2 * D + c + 1]
        + g_shift[r0 * D + c + 1] + g_shift[r1 * D + c + 1] + g_shift[r2 * D + c + 1];
    o.z = a23.x * g_scale[r0 * D + c + 2] + b23.x * g_scale[r1 * D + c + 2] + g23.x * g_scale[r2 * D + c + 2]
        + g_shift[r0 * D + c + 2] + g_shift[r1 * D + c + 2] + g_shift[r2 * D + c + 2];
    o.w = a23.y * g_scale[r0 * D + c + 3] + b23.y * g_scale[r1 * D + c + 3] + g23.y * g_scale[r2 * D + c + 3]
        + g_shift[r0 * D + c + 3] + g_shift[r1 * D + c + 3] + g_shift[r2 * D + c + 3];
    if (layer == 1) {
        const float4* rp = (type == 0) ? ra : (type == 1) ? rb : rg;
        float4 rr = rp[(size_t)local * 32 + c4];
        o.x += rr.x; o.y += rr.y; o.z += rr.z; o.w += rr.w;
        outF[i] = o;
    } else {
        ((__half2*)outH)[i * 2] = __floats2half2_rn(o.x, o.y);
        ((__half2*)outH)[i * 2 + 1] = __floats2half2_rn(o.z, o.w);
    }
}

// ---------------- cleanup ----------------
__global__ void k_cleanup() {
    int i = blockIdx.x * blockDim.x + threadIdx.x;
    int n4 = DEG_TOT / 4;
    if (i < n4) {
        ((int4*)g_odeg)[i] = make_int4(0, 0, 0, 0);
        ((int4*)g_ideg)[i] = make_int4(0, 0, 0, 0);
    }
}

// ---------------- host orchestration ----------------
static inline int cdiv(int a, int b) { return (a + b - 1) / b; }

extern "C" void kernel_launch(void* const* d_in, const int* in_sizes, int n_in,
                              void* d_out, int out_size) {
    const float* fa = (const float*)d_in[0];
    const float* fb = (const float*)d_in[1];
    const float* fg = (const float*)d_in[2];
    const float* W = (const float*)d_in[3];
    const float* gamma = (const float*)d_in[5];
    const float* beta = (const float*)d_in[6];

    EdgePtrs E;
    for (int r = 0; r < 9; r++) {
        E.s[r] = (const int*)d_in[7 + 2 * r];
        E.d[r] = (const int*)d_in[8 + 2 * r];
    }

    float* p_stats;
    __half *p_wh, *p_mh, *p_fh, *p_gout;
    cudaGetSymbolAddress((void**)&p_gout, g_gout);
    cudaGetSymbolAddress((void**)&p_stats, g_stats);
    cudaGetSymbolAddress((void**)&p_wh, g_wh);
    cudaGetSymbolAddress((void**)&p_mh, g_mh);
    cudaGetSymbolAddress((void**)&p_fh, g_fh);

    cudaFuncSetAttribute(k_gemm_all, cudaFuncAttributeMaxDynamicSharedMemorySize, SMEM_DYN);

    const int TB = 256;
    const int GGRID = DEG_TOT / 32;   // 4 rows per warp, 8 warps per block

    // 0: W->fp16 + degree count + feat->fp16
    k_prep<<<18 + EBLK + CBLK, TB>>>(E, W, (const float4*)fa, (const float4*)fb,
                                     (const float4*)fg);
    // 1: scan + ns/nd + rowinfo.deg
    k_scan1<<<SCAN_NB, 1024>>>();
    // 2: CSR fill (rowinfo.off)
    k_fill_all<<<cdiv(NE_TOT, TB), TB>>>(E);
    // 3: gather L0 (ncu target)
    k_gather_all<<<GGRID, TB>>>(p_fh);
    // 4: GEMM L0
    k_gemm_all<<<NTILES, 256, SMEM_DYN>>>(p_mh, p_wh, 0, p_gout, p_stats);
    // 5: finalize L0
    k_finalize9<<<9, 128>>>(gamma, beta);
    // 6: fuse L0 -> fp16 feat
    k_fuse_all<<<cdiv(NTOT * 32, TB), TB>>>(p_gout, (const float4*)fa, (const float4*)fb,
                                            (const float4*)fg, 0, nullptr, p_fh);
    // 7-10: layer 1
    k_gather_all<<<GGRID, TB>>>(p_fh);
    k_gemm_all<<<NTILES, 256, SMEM_DYN>>>(p_mh, p_wh, 1, p_gout, p_stats);
    k_finalize9<<<9, 128>>>(gamma + 9 * D, beta + 9 * D);
    k_fuse_all<<<cdiv(NTOT * 32, TB), TB>>>(p_gout, (const float4*)fa, (const float4*)fb,
                                            (const float4*)fg, 1, (float4*)d_out, nullptr);
    // 11: cleanup
    k_cleanup<<<cdiv(DEG_TOT / 4, TB), TB>>>();
}